// round 8
// baseline (speedup 1.0000x reference)
#include <cuda_runtime.h>
#include <cuda_bf16.h>
#include <math.h>
#include <stdint.h>

#define BATCH   2
#define SEQ     2048
#define DMODEL  2048
#define NHEADS  16
#define DHEAD   128
#define NTOK    (BATCH * SEQ)      // 4096

typedef __nv_bfloat16 bf16;

// ---------------- scratch (device globals; no allocation allowed) ----------
__device__ __align__(16) bf16 g_rhi[(size_t)NTOK * DMODEL];
__device__ __align__(16) bf16 g_rlo[(size_t)NTOK * DMODEL];
__device__ __align__(16) bf16 g_wq_hi[(size_t)NHEADS * DMODEL * DHEAD];
__device__ __align__(16) bf16 g_wq_lo[(size_t)NHEADS * DMODEL * DHEAD];
__device__ __align__(16) bf16 g_wk_hi[(size_t)NHEADS * DMODEL * DHEAD];
__device__ __align__(16) bf16 g_wk_lo[(size_t)NHEADS * DMODEL * DHEAD];
__device__ __align__(16) bf16 g_wv_hi[(size_t)NHEADS * DMODEL * DHEAD];
__device__ __align__(16) bf16 g_wv_lo[(size_t)NHEADS * DMODEL * DHEAD];
__device__ __align__(16) bf16 g_wo_hi[(size_t)DMODEL * DMODEL];
__device__ __align__(16) bf16 g_wo_lo[(size_t)DMODEL * DMODEL];
__device__ __align__(16) bf16 g_qhi[(size_t)BATCH * NHEADS * SEQ * DHEAD];
__device__ __align__(16) bf16 g_qlo[(size_t)BATCH * NHEADS * SEQ * DHEAD];
__device__ __align__(16) bf16 g_khi[(size_t)BATCH * NHEADS * SEQ * DHEAD];
__device__ __align__(16) bf16 g_klo[(size_t)BATCH * NHEADS * SEQ * DHEAD];
__device__ __align__(16) bf16 g_vhi[(size_t)BATCH * NHEADS * SEQ * DHEAD];
__device__ __align__(16) bf16 g_vlo[(size_t)BATCH * NHEADS * SEQ * DHEAD];
__device__ __align__(16) bf16 g_zhi[(size_t)BATCH * SEQ * NHEADS * DHEAD];
__device__ __align__(16) bf16 g_zlo[(size_t)BATCH * SEQ * NHEADS * DHEAD];

// ========================= helpers =========================================
__device__ __forceinline__ void ldsm_x4(uint32_t r[4], uint32_t addr) {
    asm volatile("ldmatrix.sync.aligned.m8n8.x4.shared.b16 {%0,%1,%2,%3}, [%4];"
                 : "=r"(r[0]), "=r"(r[1]), "=r"(r[2]), "=r"(r[3]) : "r"(addr));
}
__device__ __forceinline__ void ldsm_x4_t(uint32_t r[4], uint32_t addr) {
    asm volatile("ldmatrix.sync.aligned.m8n8.x4.trans.shared.b16 {%0,%1,%2,%3}, [%4];"
                 : "=r"(r[0]), "=r"(r[1]), "=r"(r[2]), "=r"(r[3]) : "r"(addr));
}
__device__ __forceinline__ void mma_bf16(float c[4], const uint32_t a[4],
                                         uint32_t b0, uint32_t b1) {
    asm volatile("mma.sync.aligned.m16n8k16.row.col.f32.bf16.bf16.f32 "
                 "{%0,%1,%2,%3}, {%4,%5,%6,%7}, {%8,%9}, {%0,%1,%2,%3};"
                 : "+f"(c[0]), "+f"(c[1]), "+f"(c[2]), "+f"(c[3])
                 : "r"(a[0]), "r"(a[1]), "r"(a[2]), "r"(a[3]), "r"(b0), "r"(b1));
}
__device__ __forceinline__ uint32_t smem_to_u32(const void* p) {
    uint32_t a;
    asm("{ .reg .u64 t; cvta.to.shared.u64 t, %1; cvt.u32.u64 %0, t; }"
        : "=r"(a) : "l"(p));
    return a;
}
__device__ __forceinline__ uint32_t pack2(bf16 lo, bf16 hi) {
    return (uint32_t)__bfloat16_as_ushort(lo) | ((uint32_t)__bfloat16_as_ushort(hi) << 16);
}
__device__ __forceinline__ void cp_async16(uint32_t dst, const void* src) {
    asm volatile("cp.async.cg.shared.global [%0], [%1], 16;" :: "r"(dst), "l"(src));
}
__device__ __forceinline__ void cp_commit() {
    asm volatile("cp.async.commit_group;" ::: "memory");
}
__device__ __forceinline__ void cp_wait0() {
    asm volatile("cp.async.wait_group 0;" ::: "memory");
}
__device__ __forceinline__ void cp_wait1() {
    asm volatile("cp.async.wait_group 1;" ::: "memory");
}
__device__ __forceinline__ void split2(float f, bf16& h, bf16& l) {
    h = __float2bfloat16(f);
    l = __float2bfloat16(f - __bfloat162float(h));
}

// ===================== conversion pre-pass (single launch) =================
__global__ __launch_bounds__(256) void convert_all(
    const float* __restrict__ resid,
    const float* __restrict__ WQ, const float* __restrict__ WK,
    const float* __restrict__ WV, const float* __restrict__ WO)
{
    const int which = blockIdx.y;
    const float* src; bf16 *hi, *lo; int n4;
    switch (which) {
        case 0: src = resid; hi = g_rhi;   lo = g_rlo;   n4 = NTOK * DMODEL / 4; break;
        case 1: src = WQ;    hi = g_wq_hi; lo = g_wq_lo; n4 = NHEADS * DMODEL * DHEAD / 4; break;
        case 2: src = WK;    hi = g_wk_hi; lo = g_wk_lo; n4 = NHEADS * DMODEL * DHEAD / 4; break;
        case 3: src = WV;    hi = g_wv_hi; lo = g_wv_lo; n4 = NHEADS * DMODEL * DHEAD / 4; break;
        default:src = WO;    hi = g_wo_hi; lo = g_wo_lo; n4 = DMODEL * DMODEL / 4; break;
    }
    int i = blockIdx.x * 256 + threadIdx.x;
    if (i >= n4) return;
    float4 v = reinterpret_cast<const float4*>(src)[i];
    bf16 hx, hy, hz, hw, lx, ly, lz, lw;
    split2(v.x, hx, lx); split2(v.y, hy, ly);
    split2(v.z, hz, lz); split2(v.w, hw, lw);
    reinterpret_cast<uint2*>(hi)[i] = make_uint2(pack2(hx, hy), pack2(hz, hw));
    reinterpret_cast<uint2*>(lo)[i] = make_uint2(pack2(lx, ly), pack2(lz, lw));
}

// ===================== pipelined split-bf16 GEMM ===========================
// 128x128 CTA tile, KT=32 k-step, 2-stage cp.async pipeline, 2 CTAs/SM.
// Stage (32KB): A-combined [128 rows x 128B: hi(64B)|lo(64B)] @0,
//               Bhi [32 x 256B] @16384, Blo @24576.
#define KT2   32
#define STG   32768
#define SM_GEMM (2 * STG)

__device__ __forceinline__ void gemm_load_stage(
    uint32_t base, const bf16* Ahi, const bf16* Alo, int lda,
    const bf16* Bhi, const bf16* Blo, int ldb, int k0, int tid)
{
    #pragma unroll
    for (int it = 0; it < 4; it++) {             // A: 1024 chunks
        int idx = tid + it * 256;
        int m  = idx >> 3;
        int c8 = idx & 7;
        uint32_t d = base + (uint32_t)(m * 128 + ((c8 ^ (m & 7)) << 4));
        const bf16* s = (c8 < 4) ? (Ahi + (size_t)m * lda + k0 + c8 * 8)
                                 : (Alo + (size_t)m * lda + k0 + (c8 - 4) * 8);
        cp_async16(d, s);
    }
    #pragma unroll
    for (int it = 0; it < 4; it++) {             // B: 1024 chunks (hi 512 + lo 512)
        int idx = tid + it * 256;
        int k   = idx >> 5;                      // 0..31
        int c8f = idx & 31;
        int c8  = c8f & 15;
        uint32_t d = base + 16384 + (c8f < 16 ? 0u : 8192u)
                   + (uint32_t)(k * 256 + ((c8 ^ (k & 7)) << 4));
        const bf16* s = ((c8f < 16) ? Bhi : Blo) + (size_t)(k0 + k) * ldb + c8 * 8;
        cp_async16(d, s);
    }
}

__device__ __forceinline__ void gemm_compute_stage(
    uint32_t base, int lane, int wm, int wn, float acc[4][4][4])
{
    #pragma unroll
    for (int k16 = 0; k16 < 2; k16++) {
        uint32_t bh[4][2], bl[4][2];
        #pragma unroll
        for (int nf = 0; nf < 2; nf++) {
            int kk = k16 * 16 + (lane & 15);
            int nn = wn + nf * 16 + ((lane >> 4) << 3);
            uint32_t off = (uint32_t)(kk * 256 + (((nn >> 3) ^ (kk & 7)) << 4));
            uint32_t r[4];
            ldsm_x4_t(r, base + 16384 + off);
            bh[nf * 2][0] = r[0]; bh[nf * 2][1] = r[1];
            bh[nf * 2 + 1][0] = r[2]; bh[nf * 2 + 1][1] = r[3];
            ldsm_x4_t(r, base + 24576 + off);
            bl[nf * 2][0] = r[0]; bl[nf * 2][1] = r[1];
            bl[nf * 2 + 1][0] = r[2]; bl[nf * 2 + 1][1] = r[3];
        }
        #pragma unroll
        for (int mi = 0; mi < 4; mi++) {
            int mm = wm + mi * 16 + (lane & 15);
            int c8 = k16 * 2 + (lane >> 4);      // 0..3
            uint32_t oh = (uint32_t)(mm * 128 + ((c8 ^ (mm & 7)) << 4));
            uint32_t ol = (uint32_t)(mm * 128 + (((c8 | 4) ^ (mm & 7)) << 4));
            uint32_t ah[4], al[4];
            ldsm_x4(ah, base + oh);
            ldsm_x4(al, base + ol);
            #pragma unroll
            for (int ni = 0; ni < 4; ni++) {
                mma_bf16(acc[mi][ni], ah, bh[ni][0], bh[ni][1]);
                mma_bf16(acc[mi][ni], ah, bl[ni][0], bl[ni][1]);
                mma_bf16(acc[mi][ni], al, bh[ni][0], bh[ni][1]);
            }
        }
    }
}

__device__ __forceinline__ void gemm_mainloop_pipe(
    const bf16* __restrict__ Ahi, const bf16* __restrict__ Alo, int lda,
    const bf16* __restrict__ Bhi, const bf16* __restrict__ Blo, int ldb,
    char* smem, float acc[4][4][4])
{
    const int tid  = threadIdx.x;
    const int lane = tid & 31;
    const int wid  = tid >> 5;
    const int wm   = (wid >> 2) * 64;
    const int wn   = (wid & 3) * 32;
    const uint32_t sb = smem_to_u32(smem);
    const int NIT = DMODEL / KT2;                // 64

    gemm_load_stage(sb, Ahi, Alo, lda, Bhi, Blo, ldb, 0, tid);
    cp_commit();

    for (int i = 0; i < NIT; i++) {
        if (i + 1 < NIT) {
            gemm_load_stage(sb + ((i + 1) & 1) * STG, Ahi, Alo, lda,
                            Bhi, Blo, ldb, (i + 1) * KT2, tid);
            cp_commit();
            cp_wait1();
        } else {
            cp_wait0();
        }
        __syncthreads();
        gemm_compute_stage(sb + (i & 1) * STG, lane, wm, wn, acc);
        __syncthreads();
    }
}

// ----------------------- QKV projection ------------------------------------
__global__ __launch_bounds__(256, 2) void qkv_tc(
    const float* __restrict__ bQ, const float* __restrict__ bK,
    const float* __restrict__ bV)
{
    extern __shared__ char smem[];
    const int i0 = blockIdx.x * 128;
    const int h  = blockIdx.y;
    const int which = blockIdx.z;

    const bf16* Whi = (which == 0) ? g_wq_hi : (which == 1) ? g_wk_hi : g_wv_hi;
    const bf16* Wlo = (which == 0) ? g_wq_lo : (which == 1) ? g_wk_lo : g_wv_lo;
    const float* bias = (which == 0) ? bQ : (which == 1) ? bK : bV;
    bf16* ohi = (which == 0) ? g_qhi : (which == 1) ? g_khi : g_vhi;
    bf16* olo = (which == 0) ? g_qlo : (which == 1) ? g_klo : g_vlo;

    float acc[4][4][4];
    #pragma unroll
    for (int mi = 0; mi < 4; mi++)
        #pragma unroll
        for (int ni = 0; ni < 4; ni++)
            #pragma unroll
            for (int j = 0; j < 4; j++) acc[mi][ni][j] = 0.0f;

    gemm_mainloop_pipe(g_rhi + (size_t)i0 * DMODEL, g_rlo + (size_t)i0 * DMODEL, DMODEL,
                       Whi + (size_t)h * DMODEL * DHEAD, Wlo + (size_t)h * DMODEL * DHEAD,
                       DHEAD, smem, acc);

    const int lane = threadIdx.x & 31;
    const int wid  = threadIdx.x >> 5;
    const int wm   = (wid >> 2) * 64;
    const int wn   = (wid & 3) * 32;
    #pragma unroll
    for (int mi = 0; mi < 4; mi++) {
        #pragma unroll
        for (int ni = 0; ni < 4; ni++) {
            int col = wn + ni * 8 + (lane & 3) * 2;
            float b0 = bias[h * DHEAD + col];
            float b1 = bias[h * DHEAD + col + 1];
            #pragma unroll
            for (int half = 0; half < 2; half++) {
                int i = i0 + wm + mi * 16 + (lane >> 2) + half * 8;
                int bb = i >> 11, s = i & 2047;
                size_t base = (((size_t)bb * NHEADS + h) * SEQ + s) * DHEAD + col;
                float f0 = acc[mi][ni][half * 2] + b0;
                float f1 = acc[mi][ni][half * 2 + 1] + b1;
                bf16 h0, h1, l0, l1;
                split2(f0, h0, l0); split2(f1, h1, l1);
                *reinterpret_cast<uint32_t*>(&ohi[base]) = pack2(h0, h1);
                *reinterpret_cast<uint32_t*>(&olo[base]) = pack2(l0, l1);
            }
        }
    }
}

// ----------------------- Output projection ---------------------------------
__global__ __launch_bounds__(256, 2) void o_tc(
    const float* __restrict__ bO, float* __restrict__ out)
{
    extern __shared__ char smem[];
    const int i0 = blockIdx.x * 128;
    const int j0 = blockIdx.y * 128;

    float acc[4][4][4];
    #pragma unroll
    for (int mi = 0; mi < 4; mi++)
        #pragma unroll
        for (int ni = 0; ni < 4; ni++)
            #pragma unroll
            for (int j = 0; j < 4; j++) acc[mi][ni][j] = 0.0f;

    gemm_mainloop_pipe(g_zhi + (size_t)i0 * DMODEL, g_zlo + (size_t)i0 * DMODEL, DMODEL,
                       g_wo_hi + j0, g_wo_lo + j0, DMODEL, smem, acc);

    const int lane = threadIdx.x & 31;
    const int wid  = threadIdx.x >> 5;
    const int wm   = (wid >> 2) * 64;
    const int wn   = (wid & 3) * 32;
    #pragma unroll
    for (int mi = 0; mi < 4; mi++) {
        #pragma unroll
        for (int ni = 0; ni < 4; ni++) {
            int col = j0 + wn + ni * 8 + (lane & 3) * 2;
            float b0 = bO[col], b1 = bO[col + 1];
            #pragma unroll
            for (int half = 0; half < 2; half++) {
                int i = i0 + wm + mi * 16 + (lane >> 2) + half * 8;
                float2 v = make_float2(acc[mi][ni][half * 2] + b0,
                                       acc[mi][ni][half * 2 + 1] + b1);
                *reinterpret_cast<float2*>(out + (size_t)i * DMODEL + col) = v;
            }
        }
    }
}

// ---------------------------------------------------------------------------
// Causal flash attention, tensor cores, 2-stage pipelined K/V.
// Stage (64KB): KHI @0, KLO @16384, VHI @32768, VLO @49152.
// ---------------------------------------------------------------------------
#define BQ2 128
#define BK2 64
#define ATSTG 65536
#define AT_SMEM (2 * ATSTG)

__device__ __forceinline__ void attn_load_kv(
    uint32_t base, const bf16* Khi, const bf16* Klo,
    const bf16* Vhi, const bf16* Vlo, int k0, int tid)
{
    #pragma unroll
    for (int it = 0; it < 4; it++) {
        int idx = tid + it * 256;                // 0..1023
        int r  = idx >> 4;
        int c8 = idx & 15;
        uint32_t d = (uint32_t)(r * 256 + ((c8 ^ (r & 7)) << 4));
        size_t so = (size_t)(k0 + r) * DHEAD + c8 * 8;
        cp_async16(base + d,         Khi + so);
        cp_async16(base + 16384 + d, Klo + so);
        cp_async16(base + 32768 + d, Vhi + so);
        cp_async16(base + 49152 + d, Vlo + so);
    }
}

__global__ __launch_bounds__(256, 1) void attn_tc()
{
    extern __shared__ char smem[];
    const uint32_t sb = smem_to_u32(smem);
    const int tid  = threadIdx.x;
    const int lane = tid & 31;
    const int w    = tid >> 5;
    const int q0   = blockIdx.x * BQ2;
    const int h    = blockIdx.y;
    const int b    = blockIdx.z;

    const size_t head_off = ((size_t)b * NHEADS + h) * SEQ * DHEAD;
    const bf16* Qhig = g_qhi + head_off + (size_t)q0 * DHEAD;
    const bf16* Qlog = g_qlo + head_off + (size_t)q0 * DHEAD;
    const bf16* Khig = g_khi + head_off;
    const bf16* Klog = g_klo + head_off;
    const bf16* Vhig = g_vhi + head_off;
    const bf16* Vlog = g_vlo + head_off;

    const int NIT = (q0 + BQ2) / BK2;

    // ---- Q into stage-1 buffer; prefetch KV tile 0 into stage-0 concurrently
    #pragma unroll
    for (int it = 0; it < 8; it++) {
        int idx = tid + it * 256;                // 0..2047
        int m  = idx >> 4;
        int c8 = idx & 15;
        uint32_t d = (uint32_t)(m * 256 + ((c8 ^ (m & 7)) << 4));
        size_t so = (size_t)m * DHEAD + c8 * 8;
        cp_async16(sb + ATSTG + d,         Qhig + so);
        cp_async16(sb + ATSTG + 32768 + d, Qlog + so);
    }
    cp_commit();
    attn_load_kv(sb, Khig, Klog, Vhig, Vlog, 0, tid);
    cp_commit();
    cp_wait1();                                  // Q ready
    __syncthreads();

    uint32_t qh[8][4], ql[8][4];
    #pragma unroll
    for (int t = 0; t < 8; t++) {
        int row = w * 16 + (lane & 15);
        int col = t * 16 + ((lane >> 4) << 3);
        uint32_t off = (uint32_t)(row * 256 + (((col >> 3) ^ (row & 7)) << 4));
        ldsm_x4(qh[t], sb + ATSTG + off);
        ldsm_x4(ql[t], sb + ATSTG + 32768 + off);
    }
    __syncthreads();                             // Q consumed; stage-1 reusable

    float O[16][4];
    #pragma unroll
    for (int nf = 0; nf < 16; nf++)
        #pragma unroll
        for (int j = 0; j < 4; j++) O[nf][j] = 0.0f;
    float m0 = -INFINITY, m1 = -INFINITY, l0 = 0.0f, l1 = 0.0f;

    const float sc_scale = 0.08838834764831843f;
    const int rbase = q0 + w * 16;

    for (int i = 0; i < NIT; i++) {
        const int k0 = i * BK2;
        if (i + 1 < NIT) {
            attn_load_kv(sb + ((i + 1) & 1) * ATSTG, Khig, Klog, Vhig, Vlog,
                         (i + 1) * BK2, tid);
            cp_commit();
            cp_wait1();
        } else {
            cp_wait0();
        }
        __syncthreads();
        const uint32_t base = sb + (i & 1) * ATSTG;

        // ---- S = Q K^T (3-pass split)
        float sf[8][4];
        #pragma unroll
        for (int nf = 0; nf < 8; nf++)
            #pragma unroll
            for (int j = 0; j < 4; j++) sf[nf][j] = 0.0f;

        #pragma unroll
        for (int t = 0; t < 8; t++) {
            #pragma unroll
            for (int nb = 0; nb < 4; nb++) {
                int row = nb * 16 + (lane & 15);
                int col = t * 16 + ((lane >> 4) << 3);
                uint32_t off = (uint32_t)(row * 256 + (((col >> 3) ^ (row & 7)) << 4));
                uint32_t kh[4], kl[4];
                ldsm_x4(kh, base + off);
                ldsm_x4(kl, base + 16384 + off);
                mma_bf16(sf[2 * nb],     qh[t], kh[0], kh[2]);
                mma_bf16(sf[2 * nb],     qh[t], kl[0], kl[2]);
                mma_bf16(sf[2 * nb],     ql[t], kh[0], kh[2]);
                mma_bf16(sf[2 * nb + 1], qh[t], kh[1], kh[3]);
                mma_bf16(sf[2 * nb + 1], qh[t], kl[1], kl[3]);
                mma_bf16(sf[2 * nb + 1], ql[t], kh[1], kh[3]);
            }
        }

        // ---- scale + causal mask
        const bool need_mask = (k0 + BK2 - 1) > (rbase);
        #pragma unroll
        for (int nf = 0; nf < 8; nf++)
            #pragma unroll
            for (int j = 0; j < 4; j++) {
                float s = sf[nf][j] * sc_scale;
                if (need_mask) {
                    int col = k0 + nf * 8 + (lane & 3) * 2 + (j & 1);
                    int row = rbase + (lane >> 2) + (j >> 1) * 8;
                    if (col > row) s = -INFINITY;
                }
                sf[nf][j] = s;
            }

        // ---- online softmax
        float mx0 = -INFINITY, mx1 = -INFINITY;
        #pragma unroll
        for (int nf = 0; nf < 8; nf++) {
            mx0 = fmaxf(mx0, fmaxf(sf[nf][0], sf[nf][1]));
            mx1 = fmaxf(mx1, fmaxf(sf[nf][2], sf[nf][3]));
        }
        mx0 = fmaxf(mx0, __shfl_xor_sync(0xffffffffu, mx0, 1));
        mx0 = fmaxf(mx0, __shfl_xor_sync(0xffffffffu, mx0, 2));
        mx1 = fmaxf(mx1, __shfl_xor_sync(0xffffffffu, mx1, 1));
        mx1 = fmaxf(mx1, __shfl_xor_sync(0xffffffffu, mx1, 2));

        float mn0 = fmaxf(m0, mx0), mn1 = fmaxf(m1, mx1);
        float cr0 = __expf(m0 - mn0), cr1 = __expf(m1 - mn1);

        float sum0 = 0.0f, sum1 = 0.0f;
        #pragma unroll
        for (int nf = 0; nf < 8; nf++) {
            float p0 = __expf(sf[nf][0] - mn0);
            float p1 = __expf(sf[nf][1] - mn0);
            float p2 = __expf(sf[nf][2] - mn1);
            float p3 = __expf(sf[nf][3] - mn1);
            sf[nf][0] = p0; sf[nf][1] = p1; sf[nf][2] = p2; sf[nf][3] = p3;
            sum0 += p0 + p1; sum1 += p2 + p3;
        }
        sum0 += __shfl_xor_sync(0xffffffffu, sum0, 1);
        sum0 += __shfl_xor_sync(0xffffffffu, sum0, 2);
        sum1 += __shfl_xor_sync(0xffffffffu, sum1, 1);
        sum1 += __shfl_xor_sync(0xffffffffu, sum1, 2);
        l0 = l0 * cr0 + sum0;  l1 = l1 * cr1 + sum1;
        m0 = mn0;  m1 = mn1;

        #pragma unroll
        for (int nf = 0; nf < 16; nf++) {
            O[nf][0] *= cr0; O[nf][1] *= cr0;
            O[nf][2] *= cr1; O[nf][3] *= cr1;
        }

        // ---- P -> A frags (hi + residual lo)
        uint32_t pa[4][4], pl[4][4];
        #pragma unroll
        for (int kb = 0; kb < 4; kb++) {
            #pragma unroll
            for (int half = 0; half < 2; half++) {
                #pragma unroll
                for (int rr = 0; rr < 2; rr++) {
                    float f0 = sf[2 * kb + half][rr * 2];
                    float f1 = sf[2 * kb + half][rr * 2 + 1];
                    bf16 h0, h1, e0, e1;
                    split2(f0, h0, e0); split2(f1, h1, e1);
                    pa[kb][half * 2 + rr] = pack2(h0, h1);
                    pl[kb][half * 2 + rr] = pack2(e0, e1);
                }
            }
        }

        // ---- O += P V (3-pass split)
        #pragma unroll
        for (int kb = 0; kb < 4; kb++) {
            #pragma unroll
            for (int nf2 = 0; nf2 < 8; nf2++) {
                int kk = kb * 16 + (lane & 15);
                int nn = nf2 * 16 + ((lane >> 4) << 3);
                uint32_t off = (uint32_t)(kk * 256 + (((nn >> 3) ^ (kk & 7)) << 4));
                uint32_t vh[4], vl[4];
                ldsm_x4_t(vh, base + 32768 + off);
                ldsm_x4_t(vl, base + 49152 + off);
                mma_bf16(O[2 * nf2],     pa[kb], vh[0], vh[1]);
                mma_bf16(O[2 * nf2],     pa[kb], vl[0], vl[1]);
                mma_bf16(O[2 * nf2],     pl[kb], vh[0], vh[1]);
                mma_bf16(O[2 * nf2 + 1], pa[kb], vh[2], vh[3]);
                mma_bf16(O[2 * nf2 + 1], pa[kb], vl[2], vl[3]);
                mma_bf16(O[2 * nf2 + 1], pl[kb], vh[2], vh[3]);
            }
        }
        __syncthreads();
    }

    // ---- normalize + write z (split hi/lo bf16) [b][s][h][d]
    float inv0 = 1.0f / l0, inv1 = 1.0f / l1;
    int r0 = rbase + (lane >> 2);
    size_t z0 = (((size_t)b * SEQ + r0) * NHEADS + h) * DHEAD;
    size_t z1 = (((size_t)b * SEQ + r0 + 8) * NHEADS + h) * DHEAD;
    #pragma unroll
    for (int nf = 0; nf < 16; nf++) {
        int col = nf * 8 + (lane & 3) * 2;
        bf16 h0, h1, e0, e1;
        split2(O[nf][0] * inv0, h0, e0);
        split2(O[nf][1] * inv0, h1, e1);
        *reinterpret_cast<uint32_t*>(&g_zhi[z0 + col]) = pack2(h0, h1);
        *reinterpret_cast<uint32_t*>(&g_zlo[z0 + col]) = pack2(e0, e1);
        split2(O[nf][2] * inv1, h0, e0);
        split2(O[nf][3] * inv1, h1, e1);
        *reinterpret_cast<uint32_t*>(&g_zhi[z1 + col]) = pack2(h0, h1);
        *reinterpret_cast<uint32_t*>(&g_zlo[z1 + col]) = pack2(e0, e1);
    }
}

// ---------------------------------------------------------------------------
extern "C" void kernel_launch(void* const* d_in, const int* in_sizes, int n_in,
                              void* d_out, int out_size)
{
    (void)in_sizes; (void)n_in; (void)out_size;
    const float* residual = (const float*)d_in[0];
    const float* WQ = (const float*)d_in[2];
    const float* WK = (const float*)d_in[3];
    const float* WV = (const float*)d_in[4];
    const float* WO = (const float*)d_in[5];
    const float* bQ = (const float*)d_in[6];
    const float* bK = (const float*)d_in[7];
    const float* bV = (const float*)d_in[8];
    const float* bO = (const float*)d_in[9];
    float* out = (float*)d_out;

    // tuple element 0: residual pass-through
    cudaMemcpyAsync(out, residual, (size_t)BATCH * SEQ * DMODEL * sizeof(float),
                    cudaMemcpyDeviceToDevice);

    // single fused conversion pre-pass
    dim3 gc(NTOK * DMODEL / 4 / 256, 5);
    convert_all<<<gc, 256>>>(residual, WQ, WK, WV, WO);

    cudaFuncSetAttribute(qkv_tc,  cudaFuncAttributeMaxDynamicSharedMemorySize, SM_GEMM);
    cudaFuncSetAttribute(o_tc,    cudaFuncAttributeMaxDynamicSharedMemorySize, SM_GEMM);
    cudaFuncSetAttribute(attn_tc, cudaFuncAttributeMaxDynamicSharedMemorySize, AT_SMEM);

    dim3 g1(NTOK / 128, NHEADS, 3);
    qkv_tc<<<g1, 256, SM_GEMM>>>(bQ, bK, bV);

    dim3 g2(SEQ / BQ2, NHEADS, BATCH);
    attn_tc<<<g2, 256, AT_SMEM>>>();

    dim3 g3(NTOK / 128, DMODEL / 128);
    o_tc<<<g3, 256, SM_GEMM>>>(bO, out + (size_t)BATCH * SEQ * DMODEL);
}

// round 9
// speedup vs baseline: 1.2914x; 1.2914x over previous
#include <cuda_runtime.h>
#include <cuda_bf16.h>
#include <cuda_fp16.h>
#include <math.h>
#include <stdint.h>

#define BATCH   2
#define SEQ     2048
#define DMODEL  2048
#define NHEADS  16
#define DHEAD   128
#define NTOK    (BATCH * SEQ)      // 4096

typedef __nv_bfloat16 bf16;

// ---------------- scratch (device globals; no allocation allowed) ----------
// fp16 split activations for projections
__device__ __align__(16) __half g_rhi[(size_t)NTOK * DMODEL];
__device__ __align__(16) __half g_rlo[(size_t)NTOK * DMODEL];
// weights: single fp16
__device__ __align__(16) __half g_wq[(size_t)NHEADS * DMODEL * DHEAD];
__device__ __align__(16) __half g_wk[(size_t)NHEADS * DMODEL * DHEAD];
__device__ __align__(16) __half g_wv[(size_t)NHEADS * DMODEL * DHEAD];
__device__ __align__(16) __half g_wo[(size_t)DMODEL * DMODEL];
// attention operands: bf16 hi/lo (3-pass path, unchanged) [b][h][s][d]
__device__ __align__(16) bf16 g_qhi[(size_t)BATCH * NHEADS * SEQ * DHEAD];
__device__ __align__(16) bf16 g_qlo[(size_t)BATCH * NHEADS * SEQ * DHEAD];
__device__ __align__(16) bf16 g_khi[(size_t)BATCH * NHEADS * SEQ * DHEAD];
__device__ __align__(16) bf16 g_klo[(size_t)BATCH * NHEADS * SEQ * DHEAD];
__device__ __align__(16) bf16 g_vhi[(size_t)BATCH * NHEADS * SEQ * DHEAD];
__device__ __align__(16) bf16 g_vlo[(size_t)BATCH * NHEADS * SEQ * DHEAD];
// attention output: fp16 hi/lo [b][s][h][d]
__device__ __align__(16) __half g_zhi[(size_t)BATCH * SEQ * NHEADS * DHEAD];
__device__ __align__(16) __half g_zlo[(size_t)BATCH * SEQ * NHEADS * DHEAD];

// ========================= helpers =========================================
__device__ __forceinline__ void ldsm_x4(uint32_t r[4], uint32_t addr) {
    asm volatile("ldmatrix.sync.aligned.m8n8.x4.shared.b16 {%0,%1,%2,%3}, [%4];"
                 : "=r"(r[0]), "=r"(r[1]), "=r"(r[2]), "=r"(r[3]) : "r"(addr));
}
__device__ __forceinline__ void ldsm_x4_t(uint32_t r[4], uint32_t addr) {
    asm volatile("ldmatrix.sync.aligned.m8n8.x4.trans.shared.b16 {%0,%1,%2,%3}, [%4];"
                 : "=r"(r[0]), "=r"(r[1]), "=r"(r[2]), "=r"(r[3]) : "r"(addr));
}
__device__ __forceinline__ void mma_bf16(float c[4], const uint32_t a[4],
                                         uint32_t b0, uint32_t b1) {
    asm volatile("mma.sync.aligned.m16n8k16.row.col.f32.bf16.bf16.f32 "
                 "{%0,%1,%2,%3}, {%4,%5,%6,%7}, {%8,%9}, {%0,%1,%2,%3};"
                 : "+f"(c[0]), "+f"(c[1]), "+f"(c[2]), "+f"(c[3])
                 : "r"(a[0]), "r"(a[1]), "r"(a[2]), "r"(a[3]), "r"(b0), "r"(b1));
}
__device__ __forceinline__ void mma_f16(float c[4], const uint32_t a[4],
                                        uint32_t b0, uint32_t b1) {
    asm volatile("mma.sync.aligned.m16n8k16.row.col.f32.f16.f16.f32 "
                 "{%0,%1,%2,%3}, {%4,%5,%6,%7}, {%8,%9}, {%0,%1,%2,%3};"
                 : "+f"(c[0]), "+f"(c[1]), "+f"(c[2]), "+f"(c[3])
                 : "r"(a[0]), "r"(a[1]), "r"(a[2]), "r"(a[3]), "r"(b0), "r"(b1));
}
__device__ __forceinline__ uint32_t smem_to_u32(const void* p) {
    uint32_t a;
    asm("{ .reg .u64 t; cvta.to.shared.u64 t, %1; cvt.u32.u64 %0, t; }"
        : "=r"(a) : "l"(p));
    return a;
}
__device__ __forceinline__ uint32_t pack2(bf16 lo, bf16 hi) {
    return (uint32_t)__bfloat16_as_ushort(lo) | ((uint32_t)__bfloat16_as_ushort(hi) << 16);
}
__device__ __forceinline__ uint32_t pack2h(__half lo, __half hi) {
    return (uint32_t)__half_as_ushort(lo) | ((uint32_t)__half_as_ushort(hi) << 16);
}
__device__ __forceinline__ void cp_async16(uint32_t dst, const void* src) {
    asm volatile("cp.async.cg.shared.global [%0], [%1], 16;" :: "r"(dst), "l"(src));
}
__device__ __forceinline__ void cp_commit() {
    asm volatile("cp.async.commit_group;" ::: "memory");
}
__device__ __forceinline__ void cp_wait0() {
    asm volatile("cp.async.wait_group 0;" ::: "memory");
}
__device__ __forceinline__ void cp_wait1() {
    asm volatile("cp.async.wait_group 1;" ::: "memory");
}
__device__ __forceinline__ void split2(float f, bf16& h, bf16& l) {
    h = __float2bfloat16(f);
    l = __float2bfloat16(f - __bfloat162float(h));
}
__device__ __forceinline__ void split2h(float f, __half& h, __half& l) {
    h = __float2half(f);
    l = __float2half(f - __half2float(h));
}

// ===================== conversion pre-pass (single launch) =================
__global__ __launch_bounds__(256) void convert_all(
    const float* __restrict__ resid,
    const float* __restrict__ WQ, const float* __restrict__ WK,
    const float* __restrict__ WV, const float* __restrict__ WO)
{
    const int which = blockIdx.y;
    int i = blockIdx.x * 256 + threadIdx.x;
    if (which == 0) {
        // residual -> fp16 hi/lo split
        int n4 = NTOK * DMODEL / 4;
        if (i >= n4) return;
        float4 v = reinterpret_cast<const float4*>(resid)[i];
        __half hx, hy, hz, hw, lx, ly, lz, lw;
        split2h(v.x, hx, lx); split2h(v.y, hy, ly);
        split2h(v.z, hz, lz); split2h(v.w, hw, lw);
        reinterpret_cast<uint2*>(g_rhi)[i] = make_uint2(pack2h(hx, hy), pack2h(hz, hw));
        reinterpret_cast<uint2*>(g_rlo)[i] = make_uint2(pack2h(lx, ly), pack2h(lz, lw));
    } else {
        // weights -> single fp16
        const float* src; __half* dst; int n4;
        switch (which) {
            case 1: src = WQ; dst = g_wq; n4 = NHEADS * DMODEL * DHEAD / 4; break;
            case 2: src = WK; dst = g_wk; n4 = NHEADS * DMODEL * DHEAD / 4; break;
            case 3: src = WV; dst = g_wv; n4 = NHEADS * DMODEL * DHEAD / 4; break;
            default:src = WO; dst = g_wo; n4 = DMODEL * DMODEL / 4; break;
        }
        if (i >= n4) return;
        float4 v = reinterpret_cast<const float4*>(src)[i];
        reinterpret_cast<uint2*>(dst)[i] =
            make_uint2(pack2h(__float2half(v.x), __float2half(v.y)),
                       pack2h(__float2half(v.z), __float2half(v.w)));
    }
}

// ===================== pipelined fp16 2-pass GEMM ==========================
// 128x128 CTA tile, KT=32 k-step, 2-stage cp.async pipeline, 2 CTAs/SM.
// Stage (24KB): A-combined [128 rows x 128B: hi(64B)|lo(64B)] @0,
//               B [32 x 256B] @16384.
#define KT2   32
#define STG   24576
#define SM_GEMM (2 * STG)

__device__ __forceinline__ void gemm_load_stage(
    uint32_t base, const __half* Ahi, const __half* Alo, int lda,
    const __half* B, int ldb, int k0, int tid)
{
    #pragma unroll
    for (int it = 0; it < 4; it++) {             // A: 1024 chunks
        int idx = tid + it * 256;
        int m  = idx >> 3;
        int c8 = idx & 7;
        uint32_t d = base + (uint32_t)(m * 128 + ((c8 ^ (m & 7)) << 4));
        const __half* s = (c8 < 4) ? (Ahi + (size_t)m * lda + k0 + c8 * 8)
                                   : (Alo + (size_t)m * lda + k0 + (c8 - 4) * 8);
        cp_async16(d, s);
    }
    #pragma unroll
    for (int it = 0; it < 2; it++) {             // B: 512 chunks
        int idx = tid + it * 256;
        int k  = idx >> 4;                       // 0..31
        int c8 = idx & 15;
        uint32_t d = base + 16384 + (uint32_t)(k * 256 + ((c8 ^ (k & 7)) << 4));
        cp_async16(d, B + (size_t)(k0 + k) * ldb + c8 * 8);
    }
}

__device__ __forceinline__ void gemm_compute_stage(
    uint32_t base, int lane, int wm, int wn, float acc[4][4][4])
{
    #pragma unroll
    for (int k16 = 0; k16 < 2; k16++) {
        uint32_t bh[4][2];
        #pragma unroll
        for (int nf = 0; nf < 2; nf++) {
            int kk = k16 * 16 + (lane & 15);
            int nn = wn + nf * 16 + ((lane >> 4) << 3);
            uint32_t off = (uint32_t)(kk * 256 + (((nn >> 3) ^ (kk & 7)) << 4));
            uint32_t r[4];
            ldsm_x4_t(r, base + 16384 + off);
            bh[nf * 2][0] = r[0]; bh[nf * 2][1] = r[1];
            bh[nf * 2 + 1][0] = r[2]; bh[nf * 2 + 1][1] = r[3];
        }
        #pragma unroll
        for (int mi = 0; mi < 4; mi++) {
            int mm = wm + mi * 16 + (lane & 15);
            int c8 = k16 * 2 + (lane >> 4);      // 0..3
            uint32_t oh = (uint32_t)(mm * 128 + ((c8 ^ (mm & 7)) << 4));
            uint32_t ol = (uint32_t)(mm * 128 + (((c8 | 4) ^ (mm & 7)) << 4));
            uint32_t ah[4], al[4];
            ldsm_x4(ah, base + oh);
            ldsm_x4(al, base + ol);
            #pragma unroll
            for (int ni = 0; ni < 4; ni++) {
                mma_f16(acc[mi][ni], ah, bh[ni][0], bh[ni][1]);
                mma_f16(acc[mi][ni], al, bh[ni][0], bh[ni][1]);
            }
        }
    }
}

__device__ __forceinline__ void gemm_mainloop_pipe(
    const __half* __restrict__ Ahi, const __half* __restrict__ Alo, int lda,
    const __half* __restrict__ B, int ldb,
    char* smem, float acc[4][4][4])
{
    const int tid  = threadIdx.x;
    const int lane = tid & 31;
    const int wid  = tid >> 5;
    const int wm   = (wid >> 2) * 64;
    const int wn   = (wid & 3) * 32;
    const uint32_t sb = smem_to_u32(smem);
    const int NIT = DMODEL / KT2;                // 64

    gemm_load_stage(sb, Ahi, Alo, lda, B, ldb, 0, tid);
    cp_commit();

    for (int i = 0; i < NIT; i++) {
        if (i + 1 < NIT) {
            gemm_load_stage(sb + ((i + 1) & 1) * STG, Ahi, Alo, lda,
                            B, ldb, (i + 1) * KT2, tid);
            cp_commit();
            cp_wait1();
        } else {
            cp_wait0();
        }
        __syncthreads();
        gemm_compute_stage(sb + (i & 1) * STG, lane, wm, wn, acc);
        __syncthreads();
    }
}

// ----------------------- QKV projection ------------------------------------
__global__ __launch_bounds__(256, 2) void qkv_tc(
    const float* __restrict__ bQ, const float* __restrict__ bK,
    const float* __restrict__ bV)
{
    extern __shared__ char smem[];
    const int i0 = blockIdx.x * 128;
    const int h  = blockIdx.y;
    const int which = blockIdx.z;

    const __half* W   = (which == 0) ? g_wq : (which == 1) ? g_wk : g_wv;
    const float* bias = (which == 0) ? bQ : (which == 1) ? bK : bV;
    bf16* ohi = (which == 0) ? g_qhi : (which == 1) ? g_khi : g_vhi;
    bf16* olo = (which == 0) ? g_qlo : (which == 1) ? g_klo : g_vlo;

    float acc[4][4][4];
    #pragma unroll
    for (int mi = 0; mi < 4; mi++)
        #pragma unroll
        for (int ni = 0; ni < 4; ni++)
            #pragma unroll
            for (int j = 0; j < 4; j++) acc[mi][ni][j] = 0.0f;

    gemm_mainloop_pipe(g_rhi + (size_t)i0 * DMODEL, g_rlo + (size_t)i0 * DMODEL, DMODEL,
                       W + (size_t)h * DMODEL * DHEAD, DHEAD, smem, acc);

    const int lane = threadIdx.x & 31;
    const int wid  = threadIdx.x >> 5;
    const int wm   = (wid >> 2) * 64;
    const int wn   = (wid & 3) * 32;
    #pragma unroll
    for (int mi = 0; mi < 4; mi++) {
        #pragma unroll
        for (int ni = 0; ni < 4; ni++) {
            int col = wn + ni * 8 + (lane & 3) * 2;
            float b0 = bias[h * DHEAD + col];
            float b1 = bias[h * DHEAD + col + 1];
            #pragma unroll
            for (int half = 0; half < 2; half++) {
                int i = i0 + wm + mi * 16 + (lane >> 2) + half * 8;
                int bb = i >> 11, s = i & 2047;
                size_t base = (((size_t)bb * NHEADS + h) * SEQ + s) * DHEAD + col;
                float f0 = acc[mi][ni][half * 2] + b0;
                float f1 = acc[mi][ni][half * 2 + 1] + b1;
                bf16 h0, h1, l0, l1;
                split2(f0, h0, l0); split2(f1, h1, l1);
                *reinterpret_cast<uint32_t*>(&ohi[base]) = pack2(h0, h1);
                *reinterpret_cast<uint32_t*>(&olo[base]) = pack2(l0, l1);
            }
        }
    }
}

// ----------------------- Output projection ---------------------------------
__global__ __launch_bounds__(256, 2) void o_tc(
    const float* __restrict__ bO, float* __restrict__ out)
{
    extern __shared__ char smem[];
    const int i0 = blockIdx.x * 128;
    const int j0 = blockIdx.y * 128;

    float acc[4][4][4];
    #pragma unroll
    for (int mi = 0; mi < 4; mi++)
        #pragma unroll
        for (int ni = 0; ni < 4; ni++)
            #pragma unroll
            for (int j = 0; j < 4; j++) acc[mi][ni][j] = 0.0f;

    gemm_mainloop_pipe(g_zhi + (size_t)i0 * DMODEL, g_zlo + (size_t)i0 * DMODEL, DMODEL,
                       g_wo + j0, DMODEL, smem, acc);

    const int lane = threadIdx.x & 31;
    const int wid  = threadIdx.x >> 5;
    const int wm   = (wid >> 2) * 64;
    const int wn   = (wid & 3) * 32;
    #pragma unroll
    for (int mi = 0; mi < 4; mi++) {
        #pragma unroll
        for (int ni = 0; ni < 4; ni++) {
            int col = j0 + wn + ni * 8 + (lane & 3) * 2;
            float b0 = bO[col], b1 = bO[col + 1];
            #pragma unroll
            for (int half = 0; half < 2; half++) {
                int i = i0 + wm + mi * 16 + (lane >> 2) + half * 8;
                float2 v = make_float2(acc[mi][ni][half * 2] + b0,
                                       acc[mi][ni][half * 2 + 1] + b1);
                *reinterpret_cast<float2*>(out + (size_t)i * DMODEL + col) = v;
            }
        }
    }
}

// ---------------------------------------------------------------------------
// Causal flash attention, tensor cores, bf16 3-pass (unchanged math),
// 2-stage pipelined K/V. Stage (64KB): KHI @0, KLO @16384, VHI @32768, VLO @49152.
// ---------------------------------------------------------------------------
#define BQ2 128
#define BK2 64
#define ATSTG 65536
#define AT_SMEM (2 * ATSTG)

__device__ __forceinline__ void attn_load_kv(
    uint32_t base, const bf16* Khi, const bf16* Klo,
    const bf16* Vhi, const bf16* Vlo, int k0, int tid)
{
    #pragma unroll
    for (int it = 0; it < 4; it++) {
        int idx = tid + it * 256;                // 0..1023
        int r  = idx >> 4;
        int c8 = idx & 15;
        uint32_t d = (uint32_t)(r * 256 + ((c8 ^ (r & 7)) << 4));
        size_t so = (size_t)(k0 + r) * DHEAD + c8 * 8;
        cp_async16(base + d,         Khi + so);
        cp_async16(base + 16384 + d, Klo + so);
        cp_async16(base + 32768 + d, Vhi + so);
        cp_async16(base + 49152 + d, Vlo + so);
    }
}

__global__ __launch_bounds__(256, 1) void attn_tc()
{
    extern __shared__ char smem[];
    const uint32_t sb = smem_to_u32(smem);
    const int tid  = threadIdx.x;
    const int lane = tid & 31;
    const int w    = tid >> 5;
    const int q0   = blockIdx.x * BQ2;
    const int h    = blockIdx.y;
    const int b    = blockIdx.z;

    const size_t head_off = ((size_t)b * NHEADS + h) * SEQ * DHEAD;
    const bf16* Qhig = g_qhi + head_off + (size_t)q0 * DHEAD;
    const bf16* Qlog = g_qlo + head_off + (size_t)q0 * DHEAD;
    const bf16* Khig = g_khi + head_off;
    const bf16* Klog = g_klo + head_off;
    const bf16* Vhig = g_vhi + head_off;
    const bf16* Vlog = g_vlo + head_off;

    const int NIT = (q0 + BQ2) / BK2;

    // ---- Q into stage-1 buffer; prefetch KV tile 0 into stage-0 concurrently
    #pragma unroll
    for (int it = 0; it < 8; it++) {
        int idx = tid + it * 256;                // 0..2047
        int m  = idx >> 4;
        int c8 = idx & 15;
        uint32_t d = (uint32_t)(m * 256 + ((c8 ^ (m & 7)) << 4));
        size_t so = (size_t)m * DHEAD + c8 * 8;
        cp_async16(sb + ATSTG + d,         Qhig + so);
        cp_async16(sb + ATSTG + 32768 + d, Qlog + so);
    }
    cp_commit();
    attn_load_kv(sb, Khig, Klog, Vhig, Vlog, 0, tid);
    cp_commit();
    cp_wait1();                                  // Q ready
    __syncthreads();

    uint32_t qh[8][4], ql[8][4];
    #pragma unroll
    for (int t = 0; t < 8; t++) {
        int row = w * 16 + (lane & 15);
        int col = t * 16 + ((lane >> 4) << 3);
        uint32_t off = (uint32_t)(row * 256 + (((col >> 3) ^ (row & 7)) << 4));
        ldsm_x4(qh[t], sb + ATSTG + off);
        ldsm_x4(ql[t], sb + ATSTG + 32768 + off);
    }
    __syncthreads();                             // Q consumed; stage-1 reusable

    float O[16][4];
    #pragma unroll
    for (int nf = 0; nf < 16; nf++)
        #pragma unroll
        for (int j = 0; j < 4; j++) O[nf][j] = 0.0f;
    float m0 = -INFINITY, m1 = -INFINITY, l0 = 0.0f, l1 = 0.0f;

    const float sc_scale = 0.08838834764831843f;
    const int rbase = q0 + w * 16;

    for (int i = 0; i < NIT; i++) {
        const int k0 = i * BK2;
        if (i + 1 < NIT) {
            attn_load_kv(sb + ((i + 1) & 1) * ATSTG, Khig, Klog, Vhig, Vlog,
                         (i + 1) * BK2, tid);
            cp_commit();
            cp_wait1();
        } else {
            cp_wait0();
        }
        __syncthreads();
        const uint32_t base = sb + (i & 1) * ATSTG;

        // ---- S = Q K^T (3-pass split)
        float sf[8][4];
        #pragma unroll
        for (int nf = 0; nf < 8; nf++)
            #pragma unroll
            for (int j = 0; j < 4; j++) sf[nf][j] = 0.0f;

        #pragma unroll
        for (int t = 0; t < 8; t++) {
            #pragma unroll
            for (int nb = 0; nb < 4; nb++) {
                int row = nb * 16 + (lane & 15);
                int col = t * 16 + ((lane >> 4) << 3);
                uint32_t off = (uint32_t)(row * 256 + (((col >> 3) ^ (row & 7)) << 4));
                uint32_t kh[4], kl[4];
                ldsm_x4(kh, base + off);
                ldsm_x4(kl, base + 16384 + off);
                mma_bf16(sf[2 * nb],     qh[t], kh[0], kh[2]);
                mma_bf16(sf[2 * nb],     qh[t], kl[0], kl[2]);
                mma_bf16(sf[2 * nb],     ql[t], kh[0], kh[2]);
                mma_bf16(sf[2 * nb + 1], qh[t], kh[1], kh[3]);
                mma_bf16(sf[2 * nb + 1], qh[t], kl[1], kl[3]);
                mma_bf16(sf[2 * nb + 1], ql[t], kh[1], kh[3]);
            }
        }

        // ---- scale + causal mask
        const bool need_mask = (k0 + BK2 - 1) > (rbase);
        #pragma unroll
        for (int nf = 0; nf < 8; nf++)
            #pragma unroll
            for (int j = 0; j < 4; j++) {
                float s = sf[nf][j] * sc_scale;
                if (need_mask) {
                    int col = k0 + nf * 8 + (lane & 3) * 2 + (j & 1);
                    int row = rbase + (lane >> 2) + (j >> 1) * 8;
                    if (col > row) s = -INFINITY;
                }
                sf[nf][j] = s;
            }

        // ---- online softmax
        float mx0 = -INFINITY, mx1 = -INFINITY;
        #pragma unroll
        for (int nf = 0; nf < 8; nf++) {
            mx0 = fmaxf(mx0, fmaxf(sf[nf][0], sf[nf][1]));
            mx1 = fmaxf(mx1, fmaxf(sf[nf][2], sf[nf][3]));
        }
        mx0 = fmaxf(mx0, __shfl_xor_sync(0xffffffffu, mx0, 1));
        mx0 = fmaxf(mx0, __shfl_xor_sync(0xffffffffu, mx0, 2));
        mx1 = fmaxf(mx1, __shfl_xor_sync(0xffffffffu, mx1, 1));
        mx1 = fmaxf(mx1, __shfl_xor_sync(0xffffffffu, mx1, 2));

        float mn0 = fmaxf(m0, mx0), mn1 = fmaxf(m1, mx1);
        float cr0 = __expf(m0 - mn0), cr1 = __expf(m1 - mn1);

        float sum0 = 0.0f, sum1 = 0.0f;
        #pragma unroll
        for (int nf = 0; nf < 8; nf++) {
            float p0 = __expf(sf[nf][0] - mn0);
            float p1 = __expf(sf[nf][1] - mn0);
            float p2 = __expf(sf[nf][2] - mn1);
            float p3 = __expf(sf[nf][3] - mn1);
            sf[nf][0] = p0; sf[nf][1] = p1; sf[nf][2] = p2; sf[nf][3] = p3;
            sum0 += p0 + p1; sum1 += p2 + p3;
        }
        sum0 += __shfl_xor_sync(0xffffffffu, sum0, 1);
        sum0 += __shfl_xor_sync(0xffffffffu, sum0, 2);
        sum1 += __shfl_xor_sync(0xffffffffu, sum1, 1);
        sum1 += __shfl_xor_sync(0xffffffffu, sum1, 2);
        l0 = l0 * cr0 + sum0;  l1 = l1 * cr1 + sum1;
        m0 = mn0;  m1 = mn1;

        #pragma unroll
        for (int nf = 0; nf < 16; nf++) {
            O[nf][0] *= cr0; O[nf][1] *= cr0;
            O[nf][2] *= cr1; O[nf][3] *= cr1;
        }

        // ---- P -> A frags (hi + residual lo)
        uint32_t pa[4][4], pl[4][4];
        #pragma unroll
        for (int kb = 0; kb < 4; kb++) {
            #pragma unroll
            for (int half = 0; half < 2; half++) {
                #pragma unroll
                for (int rr = 0; rr < 2; rr++) {
                    float f0 = sf[2 * kb + half][rr * 2];
                    float f1 = sf[2 * kb + half][rr * 2 + 1];
                    bf16 h0, h1, e0, e1;
                    split2(f0, h0, e0); split2(f1, h1, e1);
                    pa[kb][half * 2 + rr] = pack2(h0, h1);
                    pl[kb][half * 2 + rr] = pack2(e0, e1);
                }
            }
        }

        // ---- O += P V (3-pass split)
        #pragma unroll
        for (int kb = 0; kb < 4; kb++) {
            #pragma unroll
            for (int nf2 = 0; nf2 < 8; nf2++) {
                int kk = kb * 16 + (lane & 15);
                int nn = nf2 * 16 + ((lane >> 4) << 3);
                uint32_t off = (uint32_t)(kk * 256 + (((nn >> 3) ^ (kk & 7)) << 4));
                uint32_t vh[4], vl[4];
                ldsm_x4_t(vh, base + 32768 + off);
                ldsm_x4_t(vl, base + 49152 + off);
                mma_bf16(O[2 * nf2],     pa[kb], vh[0], vh[1]);
                mma_bf16(O[2 * nf2],     pa[kb], vl[0], vl[1]);
                mma_bf16(O[2 * nf2],     pl[kb], vh[0], vh[1]);
                mma_bf16(O[2 * nf2 + 1], pa[kb], vh[2], vh[3]);
                mma_bf16(O[2 * nf2 + 1], pa[kb], vl[2], vl[3]);
                mma_bf16(O[2 * nf2 + 1], pl[kb], vh[2], vh[3]);
            }
        }
        __syncthreads();
    }

    // ---- normalize + write z (fp16 hi/lo split) [b][s][h][d]
    float inv0 = 1.0f / l0, inv1 = 1.0f / l1;
    int r0 = rbase + (lane >> 2);
    size_t z0 = (((size_t)b * SEQ + r0) * NHEADS + h) * DHEAD;
    size_t z1 = (((size_t)b * SEQ + r0 + 8) * NHEADS + h) * DHEAD;
    #pragma unroll
    for (int nf = 0; nf < 16; nf++) {
        int col = nf * 8 + (lane & 3) * 2;
        __half h0, h1, e0, e1;
        split2h(O[nf][0] * inv0, h0, e0);
        split2h(O[nf][1] * inv0, h1, e1);
        *reinterpret_cast<uint32_t*>(&g_zhi[z0 + col]) = pack2h(h0, h1);
        *reinterpret_cast<uint32_t*>(&g_zlo[z0 + col]) = pack2h(e0, e1);
        split2h(O[nf][2] * inv1, h0, e0);
        split2h(O[nf][3] * inv1, h1, e1);
        *reinterpret_cast<uint32_t*>(&g_zhi[z1 + col]) = pack2h(h0, h1);
        *reinterpret_cast<uint32_t*>(&g_zlo[z1 + col]) = pack2h(e0, e1);
    }
}

// ---------------------------------------------------------------------------
extern "C" void kernel_launch(void* const* d_in, const int* in_sizes, int n_in,
                              void* d_out, int out_size)
{
    (void)in_sizes; (void)n_in; (void)out_size;
    const float* residual = (const float*)d_in[0];
    const float* WQ = (const float*)d_in[2];
    const float* WK = (const float*)d_in[3];
    const float* WV = (const float*)d_in[4];
    const float* WO = (const float*)d_in[5];
    const float* bQ = (const float*)d_in[6];
    const float* bK = (const float*)d_in[7];
    const float* bV = (const float*)d_in[8];
    const float* bO = (const float*)d_in[9];
    float* out = (float*)d_out;

    // tuple element 0: residual pass-through
    cudaMemcpyAsync(out, residual, (size_t)BATCH * SEQ * DMODEL * sizeof(float),
                    cudaMemcpyDeviceToDevice);

    // single fused conversion pre-pass
    dim3 gc(NTOK * DMODEL / 4 / 256, 5);
    convert_all<<<gc, 256>>>(residual, WQ, WK, WV, WO);

    cudaFuncSetAttribute(qkv_tc,  cudaFuncAttributeMaxDynamicSharedMemorySize, SM_GEMM);
    cudaFuncSetAttribute(o_tc,    cudaFuncAttributeMaxDynamicSharedMemorySize, SM_GEMM);
    cudaFuncSetAttribute(attn_tc, cudaFuncAttributeMaxDynamicSharedMemorySize, AT_SMEM);

    dim3 g1(NTOK / 128, NHEADS, 3);
    qkv_tc<<<g1, 256, SM_GEMM>>>(bQ, bK, bV);

    dim3 g2(SEQ / BQ2, NHEADS, BATCH);
    attn_tc<<<g2, 256, AT_SMEM>>>();

    dim3 g3(NTOK / 128, DMODEL / 128);
    o_tc<<<g3, 256, SM_GEMM>>>(bO, out + (size_t)BATCH * SEQ * DMODEL);
}

// round 10
// speedup vs baseline: 1.4462x; 1.1199x over previous
#include <cuda_runtime.h>
#include <cuda_bf16.h>
#include <cuda_fp16.h>
#include <math.h>
#include <stdint.h>

#define BATCH   2
#define SEQ     2048
#define DMODEL  2048
#define NHEADS  16
#define DHEAD   128
#define NTOK    (BATCH * SEQ)      // 4096

// ---------------- scratch (device globals; no allocation allowed) ----------
// fp16 split activations for projections
__device__ __align__(16) __half g_rhi[(size_t)NTOK * DMODEL];
__device__ __align__(16) __half g_rlo[(size_t)NTOK * DMODEL];
// weights: single fp16
__device__ __align__(16) __half g_wq[(size_t)NHEADS * DMODEL * DHEAD];
__device__ __align__(16) __half g_wk[(size_t)NHEADS * DMODEL * DHEAD];
__device__ __align__(16) __half g_wv[(size_t)NHEADS * DMODEL * DHEAD];
__device__ __align__(16) __half g_wo[(size_t)DMODEL * DMODEL];
// attention operands [b][h][s][d]: Q split fp16, K/V single fp16
__device__ __align__(16) __half g_qhi[(size_t)BATCH * NHEADS * SEQ * DHEAD];
__device__ __align__(16) __half g_qlo[(size_t)BATCH * NHEADS * SEQ * DHEAD];
__device__ __align__(16) __half g_k  [(size_t)BATCH * NHEADS * SEQ * DHEAD];
__device__ __align__(16) __half g_v  [(size_t)BATCH * NHEADS * SEQ * DHEAD];
// attention output: fp16 hi/lo [b][s][h][d]
__device__ __align__(16) __half g_zhi[(size_t)BATCH * SEQ * NHEADS * DHEAD];
__device__ __align__(16) __half g_zlo[(size_t)BATCH * SEQ * NHEADS * DHEAD];

// ========================= helpers =========================================
__device__ __forceinline__ void ldsm_x4(uint32_t r[4], uint32_t addr) {
    asm volatile("ldmatrix.sync.aligned.m8n8.x4.shared.b16 {%0,%1,%2,%3}, [%4];"
                 : "=r"(r[0]), "=r"(r[1]), "=r"(r[2]), "=r"(r[3]) : "r"(addr));
}
__device__ __forceinline__ void ldsm_x4_t(uint32_t r[4], uint32_t addr) {
    asm volatile("ldmatrix.sync.aligned.m8n8.x4.trans.shared.b16 {%0,%1,%2,%3}, [%4];"
                 : "=r"(r[0]), "=r"(r[1]), "=r"(r[2]), "=r"(r[3]) : "r"(addr));
}
__device__ __forceinline__ void mma_f16(float c[4], const uint32_t a[4],
                                        uint32_t b0, uint32_t b1) {
    asm volatile("mma.sync.aligned.m16n8k16.row.col.f32.f16.f16.f32 "
                 "{%0,%1,%2,%3}, {%4,%5,%6,%7}, {%8,%9}, {%0,%1,%2,%3};"
                 : "+f"(c[0]), "+f"(c[1]), "+f"(c[2]), "+f"(c[3])
                 : "r"(a[0]), "r"(a[1]), "r"(a[2]), "r"(a[3]), "r"(b0), "r"(b1));
}
__device__ __forceinline__ uint32_t smem_to_u32(const void* p) {
    uint32_t a;
    asm("{ .reg .u64 t; cvta.to.shared.u64 t, %1; cvt.u32.u64 %0, t; }"
        : "=r"(a) : "l"(p));
    return a;
}
__device__ __forceinline__ uint32_t pack2h(__half lo, __half hi) {
    return (uint32_t)__half_as_ushort(lo) | ((uint32_t)__half_as_ushort(hi) << 16);
}
__device__ __forceinline__ void cp_async16(uint32_t dst, const void* src) {
    asm volatile("cp.async.cg.shared.global [%0], [%1], 16;" :: "r"(dst), "l"(src));
}
__device__ __forceinline__ void cp_commit() {
    asm volatile("cp.async.commit_group;" ::: "memory");
}
__device__ __forceinline__ void cp_wait0() {
    asm volatile("cp.async.wait_group 0;" ::: "memory");
}
__device__ __forceinline__ void cp_wait1() {
    asm volatile("cp.async.wait_group 1;" ::: "memory");
}
__device__ __forceinline__ void split2h(float f, __half& h, __half& l) {
    h = __float2half(f);
    l = __float2half(f - __half2float(h));
}

// ===================== conversion pre-pass (single launch) =================
__global__ __launch_bounds__(256) void convert_all(
    const float* __restrict__ resid,
    const float* __restrict__ WQ, const float* __restrict__ WK,
    const float* __restrict__ WV, const float* __restrict__ WO)
{
    const int which = blockIdx.y;
    int i = blockIdx.x * 256 + threadIdx.x;
    if (which == 0) {
        int n4 = NTOK * DMODEL / 4;
        if (i >= n4) return;
        float4 v = reinterpret_cast<const float4*>(resid)[i];
        __half hx, hy, hz, hw, lx, ly, lz, lw;
        split2h(v.x, hx, lx); split2h(v.y, hy, ly);
        split2h(v.z, hz, lz); split2h(v.w, hw, lw);
        reinterpret_cast<uint2*>(g_rhi)[i] = make_uint2(pack2h(hx, hy), pack2h(hz, hw));
        reinterpret_cast<uint2*>(g_rlo)[i] = make_uint2(pack2h(lx, ly), pack2h(lz, lw));
    } else {
        const float* src; __half* dst; int n4;
        switch (which) {
            case 1: src = WQ; dst = g_wq; n4 = NHEADS * DMODEL * DHEAD / 4; break;
            case 2: src = WK; dst = g_wk; n4 = NHEADS * DMODEL * DHEAD / 4; break;
            case 3: src = WV; dst = g_wv; n4 = NHEADS * DMODEL * DHEAD / 4; break;
            default:src = WO; dst = g_wo; n4 = DMODEL * DMODEL / 4; break;
        }
        if (i >= n4) return;
        float4 v = reinterpret_cast<const float4*>(src)[i];
        reinterpret_cast<uint2*>(dst)[i] =
            make_uint2(pack2h(__float2half(v.x), __float2half(v.y)),
                       pack2h(__float2half(v.z), __float2half(v.w)));
    }
}

// ===================== pipelined fp16 2-pass GEMM (unchanged R9) ===========
#define KT2   32
#define STG   24576
#define SM_GEMM (2 * STG)

__device__ __forceinline__ void gemm_load_stage(
    uint32_t base, const __half* Ahi, const __half* Alo, int lda,
    const __half* B, int ldb, int k0, int tid)
{
    #pragma unroll
    for (int it = 0; it < 4; it++) {
        int idx = tid + it * 256;
        int m  = idx >> 3;
        int c8 = idx & 7;
        uint32_t d = base + (uint32_t)(m * 128 + ((c8 ^ (m & 7)) << 4));
        const __half* s = (c8 < 4) ? (Ahi + (size_t)m * lda + k0 + c8 * 8)
                                   : (Alo + (size_t)m * lda + k0 + (c8 - 4) * 8);
        cp_async16(d, s);
    }
    #pragma unroll
    for (int it = 0; it < 2; it++) {
        int idx = tid + it * 256;
        int k  = idx >> 4;
        int c8 = idx & 15;
        uint32_t d = base + 16384 + (uint32_t)(k * 256 + ((c8 ^ (k & 7)) << 4));
        cp_async16(d, B + (size_t)(k0 + k) * ldb + c8 * 8);
    }
}

__device__ __forceinline__ void gemm_compute_stage(
    uint32_t base, int lane, int wm, int wn, float acc[4][4][4])
{
    #pragma unroll
    for (int k16 = 0; k16 < 2; k16++) {
        uint32_t bh[4][2];
        #pragma unroll
        for (int nf = 0; nf < 2; nf++) {
            int kk = k16 * 16 + (lane & 15);
            int nn = wn + nf * 16 + ((lane >> 4) << 3);
            uint32_t off = (uint32_t)(kk * 256 + (((nn >> 3) ^ (kk & 7)) << 4));
            uint32_t r[4];
            ldsm_x4_t(r, base + 16384 + off);
            bh[nf * 2][0] = r[0]; bh[nf * 2][1] = r[1];
            bh[nf * 2 + 1][0] = r[2]; bh[nf * 2 + 1][1] = r[3];
        }
        #pragma unroll
        for (int mi = 0; mi < 4; mi++) {
            int mm = wm + mi * 16 + (lane & 15);
            int c8 = k16 * 2 + (lane >> 4);
            uint32_t oh = (uint32_t)(mm * 128 + ((c8 ^ (mm & 7)) << 4));
            uint32_t ol = (uint32_t)(mm * 128 + (((c8 | 4) ^ (mm & 7)) << 4));
            uint32_t ah[4], al[4];
            ldsm_x4(ah, base + oh);
            ldsm_x4(al, base + ol);
            #pragma unroll
            for (int ni = 0; ni < 4; ni++) {
                mma_f16(acc[mi][ni], ah, bh[ni][0], bh[ni][1]);
                mma_f16(acc[mi][ni], al, bh[ni][0], bh[ni][1]);
            }
        }
    }
}

__device__ __forceinline__ void gemm_mainloop_pipe(
    const __half* __restrict__ Ahi, const __half* __restrict__ Alo, int lda,
    const __half* __restrict__ B, int ldb,
    char* smem, float acc[4][4][4])
{
    const int tid  = threadIdx.x;
    const int lane = tid & 31;
    const int wid  = tid >> 5;
    const int wm   = (wid >> 2) * 64;
    const int wn   = (wid & 3) * 32;
    const uint32_t sb = smem_to_u32(smem);
    const int NIT = DMODEL / KT2;

    gemm_load_stage(sb, Ahi, Alo, lda, B, ldb, 0, tid);
    cp_commit();

    for (int i = 0; i < NIT; i++) {
        if (i + 1 < NIT) {
            gemm_load_stage(sb + ((i + 1) & 1) * STG, Ahi, Alo, lda,
                            B, ldb, (i + 1) * KT2, tid);
            cp_commit();
            cp_wait1();
        } else {
            cp_wait0();
        }
        __syncthreads();
        gemm_compute_stage(sb + (i & 1) * STG, lane, wm, wn, acc);
        __syncthreads();
    }
}

// ----------------------- QKV projection ------------------------------------
__global__ __launch_bounds__(256, 2) void qkv_tc(
    const float* __restrict__ bQ, const float* __restrict__ bK,
    const float* __restrict__ bV)
{
    extern __shared__ char smem[];
    const int i0 = blockIdx.x * 128;
    const int h  = blockIdx.y;
    const int which = blockIdx.z;

    const __half* W   = (which == 0) ? g_wq : (which == 1) ? g_wk : g_wv;
    const float* bias = (which == 0) ? bQ : (which == 1) ? bK : bV;

    float acc[4][4][4];
    #pragma unroll
    for (int mi = 0; mi < 4; mi++)
        #pragma unroll
        for (int ni = 0; ni < 4; ni++)
            #pragma unroll
            for (int j = 0; j < 4; j++) acc[mi][ni][j] = 0.0f;

    gemm_mainloop_pipe(g_rhi + (size_t)i0 * DMODEL, g_rlo + (size_t)i0 * DMODEL, DMODEL,
                       W + (size_t)h * DMODEL * DHEAD, DHEAD, smem, acc);

    const int lane = threadIdx.x & 31;
    const int wid  = threadIdx.x >> 5;
    const int wm   = (wid >> 2) * 64;
    const int wn   = (wid & 3) * 32;
    #pragma unroll
    for (int mi = 0; mi < 4; mi++) {
        #pragma unroll
        for (int ni = 0; ni < 4; ni++) {
            int col = wn + ni * 8 + (lane & 3) * 2;
            float b0 = bias[h * DHEAD + col];
            float b1 = bias[h * DHEAD + col + 1];
            #pragma unroll
            for (int half = 0; half < 2; half++) {
                int i = i0 + wm + mi * 16 + (lane >> 2) + half * 8;
                int bb = i >> 11, s = i & 2047;
                size_t base = (((size_t)bb * NHEADS + h) * SEQ + s) * DHEAD + col;
                float f0 = acc[mi][ni][half * 2] + b0;
                float f1 = acc[mi][ni][half * 2 + 1] + b1;
                if (which == 0) {
                    __half h0, h1, l0, l1;
                    split2h(f0, h0, l0); split2h(f1, h1, l1);
                    *reinterpret_cast<uint32_t*>(&g_qhi[base]) = pack2h(h0, h1);
                    *reinterpret_cast<uint32_t*>(&g_qlo[base]) = pack2h(l0, l1);
                } else {
                    __half* dst = (which == 1) ? g_k : g_v;
                    *reinterpret_cast<uint32_t*>(&dst[base]) =
                        pack2h(__float2half(f0), __float2half(f1));
                }
            }
        }
    }
}

// ----------------------- Output projection ---------------------------------
__global__ __launch_bounds__(256, 2) void o_tc(
    const float* __restrict__ bO, float* __restrict__ out)
{
    extern __shared__ char smem[];
    const int i0 = blockIdx.x * 128;
    const int j0 = blockIdx.y * 128;

    float acc[4][4][4];
    #pragma unroll
    for (int mi = 0; mi < 4; mi++)
        #pragma unroll
        for (int ni = 0; ni < 4; ni++)
            #pragma unroll
            for (int j = 0; j < 4; j++) acc[mi][ni][j] = 0.0f;

    gemm_mainloop_pipe(g_zhi + (size_t)i0 * DMODEL, g_zlo + (size_t)i0 * DMODEL, DMODEL,
                       g_wo + j0, DMODEL, smem, acc);

    const int lane = threadIdx.x & 31;
    const int wid  = threadIdx.x >> 5;
    const int wm   = (wid >> 2) * 64;
    const int wn   = (wid & 3) * 32;
    #pragma unroll
    for (int mi = 0; mi < 4; mi++) {
        #pragma unroll
        for (int ni = 0; ni < 4; ni++) {
            int col = j0 + wn + ni * 8 + (lane & 3) * 2;
            float b0 = bO[col], b1 = bO[col + 1];
            #pragma unroll
            for (int half = 0; half < 2; half++) {
                int i = i0 + wm + mi * 16 + (lane >> 2) + half * 8;
                float2 v = make_float2(acc[mi][ni][half * 2] + b0,
                                       acc[mi][ni][half * 2 + 1] + b1);
                *reinterpret_cast<float2*>(out + (size_t)i * DMODEL + col) = v;
            }
        }
    }
}

// ---------------------------------------------------------------------------
// Causal flash attention, fp16 2-pass both GEMMs.
// S = (Qhi+Qlo)·K (K single fp16);  O = (Phi+Plo)·V (V single fp16).
// Stage (32KB): K @0 (16KB), V @16384. 2 stages = 64KB.
// ---------------------------------------------------------------------------
#define BQ2 128
#define BK2 64
#define ATSTG 32768
#define AT_SMEM (2 * ATSTG)

__device__ __forceinline__ void attn_load_kv(
    uint32_t base, const __half* Kg, const __half* Vg, int k0, int tid)
{
    #pragma unroll
    for (int it = 0; it < 4; it++) {
        int idx = tid + it * 256;                // 0..1023
        int r  = idx >> 4;
        int c8 = idx & 15;
        uint32_t d = (uint32_t)(r * 256 + ((c8 ^ (r & 7)) << 4));
        size_t so = (size_t)(k0 + r) * DHEAD + c8 * 8;
        cp_async16(base + d,         Kg + so);
        cp_async16(base + 16384 + d, Vg + so);
    }
}

__global__ __launch_bounds__(256, 1) void attn_tc()
{
    extern __shared__ char smem[];
    const uint32_t sb = smem_to_u32(smem);
    const int tid  = threadIdx.x;
    const int lane = tid & 31;
    const int w    = tid >> 5;
    const int q0   = blockIdx.x * BQ2;
    const int h    = blockIdx.y;
    const int b    = blockIdx.z;

    const size_t head_off = ((size_t)b * NHEADS + h) * SEQ * DHEAD;
    const __half* Qhig = g_qhi + head_off + (size_t)q0 * DHEAD;
    const __half* Qlog = g_qlo + head_off + (size_t)q0 * DHEAD;
    const __half* Kg   = g_k   + head_off;
    const __half* Vg   = g_v   + head_off;

    const int NIT = (q0 + BQ2) / BK2;

    // ---- Q prologue: fill both stage buffers with Q hi (stage0) / lo (stage1)
    #pragma unroll
    for (int it = 0; it < 8; it++) {
        int idx = tid + it * 256;                // 0..2047
        int m  = idx >> 4;
        int c8 = idx & 15;
        uint32_t d = (uint32_t)(m * 256 + ((c8 ^ (m & 7)) << 4));
        size_t so = (size_t)m * DHEAD + c8 * 8;
        cp_async16(sb + d,         Qhig + so);
        cp_async16(sb + ATSTG + d, Qlog + so);
    }
    cp_commit();
    cp_wait0();
    __syncthreads();

    uint32_t qh[8][4], ql[8][4];
    #pragma unroll
    for (int t = 0; t < 8; t++) {
        int row = w * 16 + (lane & 15);
        int col = t * 16 + ((lane >> 4) << 3);
        uint32_t off = (uint32_t)(row * 256 + (((col >> 3) ^ (row & 7)) << 4));
        ldsm_x4(qh[t], sb + off);
        ldsm_x4(ql[t], sb + ATSTG + off);
    }
    __syncthreads();                             // Q consumed; smem reusable

    // prefetch KV tile 0
    attn_load_kv(sb, Kg, Vg, 0, tid);
    cp_commit();

    float O[16][4];
    #pragma unroll
    for (int nf = 0; nf < 16; nf++)
        #pragma unroll
        for (int j = 0; j < 4; j++) O[nf][j] = 0.0f;
    float m0 = -INFINITY, m1 = -INFINITY, l0 = 0.0f, l1 = 0.0f;

    const float sc_scale = 0.08838834764831843f;
    const int rbase = q0 + w * 16;

    for (int i = 0; i < NIT; i++) {
        const int k0 = i * BK2;
        if (i + 1 < NIT) {
            attn_load_kv(sb + ((i + 1) & 1) * ATSTG, Kg, Vg, (i + 1) * BK2, tid);
            cp_commit();
            cp_wait1();
        } else {
            cp_wait0();
        }
        __syncthreads();
        const uint32_t base = sb + (i & 1) * ATSTG;

        // ---- S = Q K^T (fp16 2-pass)
        float sf[8][4];
        #pragma unroll
        for (int nf = 0; nf < 8; nf++)
            #pragma unroll
            for (int j = 0; j < 4; j++) sf[nf][j] = 0.0f;

        #pragma unroll
        for (int t = 0; t < 8; t++) {
            #pragma unroll
            for (int nb = 0; nb < 4; nb++) {
                int row = nb * 16 + (lane & 15);
                int col = t * 16 + ((lane >> 4) << 3);
                uint32_t off = (uint32_t)(row * 256 + (((col >> 3) ^ (row & 7)) << 4));
                uint32_t kh[4];
                ldsm_x4(kh, base + off);
                mma_f16(sf[2 * nb],     qh[t], kh[0], kh[2]);
                mma_f16(sf[2 * nb],     ql[t], kh[0], kh[2]);
                mma_f16(sf[2 * nb + 1], qh[t], kh[1], kh[3]);
                mma_f16(sf[2 * nb + 1], ql[t], kh[1], kh[3]);
            }
        }

        // ---- scale + causal mask
        const bool need_mask = (k0 + BK2 - 1) > (rbase);
        #pragma unroll
        for (int nf = 0; nf < 8; nf++)
            #pragma unroll
            for (int j = 0; j < 4; j++) {
                float s = sf[nf][j] * sc_scale;
                if (need_mask) {
                    int col = k0 + nf * 8 + (lane & 3) * 2 + (j & 1);
                    int row = rbase + (lane >> 2) + (j >> 1) * 8;
                    if (col > row) s = -INFINITY;
                }
                sf[nf][j] = s;
            }

        // ---- online softmax
        float mx0 = -INFINITY, mx1 = -INFINITY;
        #pragma unroll
        for (int nf = 0; nf < 8; nf++) {
            mx0 = fmaxf(mx0, fmaxf(sf[nf][0], sf[nf][1]));
            mx1 = fmaxf(mx1, fmaxf(sf[nf][2], sf[nf][3]));
        }
        mx0 = fmaxf(mx0, __shfl_xor_sync(0xffffffffu, mx0, 1));
        mx0 = fmaxf(mx0, __shfl_xor_sync(0xffffffffu, mx0, 2));
        mx1 = fmaxf(mx1, __shfl_xor_sync(0xffffffffu, mx1, 1));
        mx1 = fmaxf(mx1, __shfl_xor_sync(0xffffffffu, mx1, 2));

        float mn0 = fmaxf(m0, mx0), mn1 = fmaxf(m1, mx1);
        float cr0 = __expf(m0 - mn0), cr1 = __expf(m1 - mn1);

        float sum0 = 0.0f, sum1 = 0.0f;
        #pragma unroll
        for (int nf = 0; nf < 8; nf++) {
            float p0 = __expf(sf[nf][0] - mn0);
            float p1 = __expf(sf[nf][1] - mn0);
            float p2 = __expf(sf[nf][2] - mn1);
            float p3 = __expf(sf[nf][3] - mn1);
            sf[nf][0] = p0; sf[nf][1] = p1; sf[nf][2] = p2; sf[nf][3] = p3;
            sum0 += p0 + p1; sum1 += p2 + p3;
        }
        sum0 += __shfl_xor_sync(0xffffffffu, sum0, 1);
        sum0 += __shfl_xor_sync(0xffffffffu, sum0, 2);
        sum1 += __shfl_xor_sync(0xffffffffu, sum1, 1);
        sum1 += __shfl_xor_sync(0xffffffffu, sum1, 2);
        l0 = l0 * cr0 + sum0;  l1 = l1 * cr1 + sum1;
        m0 = mn0;  m1 = mn1;

        #pragma unroll
        for (int nf = 0; nf < 16; nf++) {
            O[nf][0] *= cr0; O[nf][1] *= cr0;
            O[nf][2] *= cr1; O[nf][3] *= cr1;
        }

        // ---- P -> A frags (fp16 hi + residual lo)
        uint32_t pa[4][4], pl[4][4];
        #pragma unroll
        for (int kb = 0; kb < 4; kb++) {
            #pragma unroll
            for (int half = 0; half < 2; half++) {
                #pragma unroll
                for (int rr = 0; rr < 2; rr++) {
                    float f0 = sf[2 * kb + half][rr * 2];
                    float f1 = sf[2 * kb + half][rr * 2 + 1];
                    __half h0, h1, e0, e1;
                    split2h(f0, h0, e0); split2h(f1, h1, e1);
                    pa[kb][half * 2 + rr] = pack2h(h0, h1);
                    pl[kb][half * 2 + rr] = pack2h(e0, e1);
                }
            }
        }

        // ---- O += P V (fp16 2-pass)
        #pragma unroll
        for (int kb = 0; kb < 4; kb++) {
            #pragma unroll
            for (int nf2 = 0; nf2 < 8; nf2++) {
                int kk = kb * 16 + (lane & 15);
                int nn = nf2 * 16 + ((lane >> 4) << 3);
                uint32_t off = (uint32_t)(kk * 256 + (((nn >> 3) ^ (kk & 7)) << 4));
                uint32_t vh[4];
                ldsm_x4_t(vh, base + 16384 + off);
                mma_f16(O[2 * nf2],     pa[kb], vh[0], vh[1]);
                mma_f16(O[2 * nf2],     pl[kb], vh[0], vh[1]);
                mma_f16(O[2 * nf2 + 1], pa[kb], vh[2], vh[3]);
                mma_f16(O[2 * nf2 + 1], pl[kb], vh[2], vh[3]);
            }
        }
        __syncthreads();
    }

    // ---- normalize + write z (fp16 hi/lo split) [b][s][h][d]
    float inv0 = 1.0f / l0, inv1 = 1.0f / l1;
    int r0 = rbase + (lane >> 2);
    size_t z0 = (((size_t)b * SEQ + r0) * NHEADS + h) * DHEAD;
    size_t z1 = (((size_t)b * SEQ + r0 + 8) * NHEADS + h) * DHEAD;
    #pragma unroll
    for (int nf = 0; nf < 16; nf++) {
        int col = nf * 8 + (lane & 3) * 2;
        __half h0, h1, e0, e1;
        split2h(O[nf][0] * inv0, h0, e0);
        split2h(O[nf][1] * inv0, h1, e1);
        *reinterpret_cast<uint32_t*>(&g_zhi[z0 + col]) = pack2h(h0, h1);
        *reinterpret_cast<uint32_t*>(&g_zlo[z0 + col]) = pack2h(e0, e1);
        split2h(O[nf][2] * inv1, h0, e0);
        split2h(O[nf][3] * inv1, h1, e1);
        *reinterpret_cast<uint32_t*>(&g_zhi[z1 + col]) = pack2h(h0, h1);
        *reinterpret_cast<uint32_t*>(&g_zlo[z1 + col]) = pack2h(e0, e1);
    }
}

// ---------------------------------------------------------------------------
extern "C" void kernel_launch(void* const* d_in, const int* in_sizes, int n_in,
                              void* d_out, int out_size)
{
    (void)in_sizes; (void)n_in; (void)out_size;
    const float* residual = (const float*)d_in[0];
    const float* WQ = (const float*)d_in[2];
    const float* WK = (const float*)d_in[3];
    const float* WV = (const float*)d_in[4];
    const float* WO = (const float*)d_in[5];
    const float* bQ = (const float*)d_in[6];
    const float* bK = (const float*)d_in[7];
    const float* bV = (const float*)d_in[8];
    const float* bO = (const float*)d_in[9];
    float* out = (float*)d_out;

    // tuple element 0: residual pass-through
    cudaMemcpyAsync(out, residual, (size_t)BATCH * SEQ * DMODEL * sizeof(float),
                    cudaMemcpyDeviceToDevice);

    // single fused conversion pre-pass
    dim3 gc(NTOK * DMODEL / 4 / 256, 5);
    convert_all<<<gc, 256>>>(residual, WQ, WK, WV, WO);

    cudaFuncSetAttribute(qkv_tc,  cudaFuncAttributeMaxDynamicSharedMemorySize, SM_GEMM);
    cudaFuncSetAttribute(o_tc,    cudaFuncAttributeMaxDynamicSharedMemorySize, SM_GEMM);
    cudaFuncSetAttribute(attn_tc, cudaFuncAttributeMaxDynamicSharedMemorySize, AT_SMEM);

    dim3 g1(NTOK / 128, NHEADS, 3);
    qkv_tc<<<g1, 256, SM_GEMM>>>(bQ, bK, bV);

    dim3 g2(SEQ / BQ2, NHEADS, BATCH);
    attn_tc<<<g2, 256, AT_SMEM>>>();

    dim3 g3(NTOK / 128, DMODEL / 128);
    o_tc<<<g3, 256, SM_GEMM>>>(bO, out + (size_t)BATCH * SEQ * DMODEL);
}

// round 11
// speedup vs baseline: 1.9060x; 1.3179x over previous
#include <cuda_runtime.h>
#include <cuda_bf16.h>
#include <cuda_fp16.h>
#include <math.h>
#include <stdint.h>

#define BATCH   2
#define SEQ     2048
#define DMODEL  2048
#define NHEADS  16
#define DHEAD   128
#define NTOK    (BATCH * SEQ)      // 4096

// ---------------- scratch (device globals; no allocation allowed) ----------
// residual: single fp16 (qkv is single-pass now)
__device__ __align__(16) __half g_r[(size_t)NTOK * DMODEL];
// weights: single fp16
__device__ __align__(16) __half g_wq[(size_t)NHEADS * DMODEL * DHEAD];
__device__ __align__(16) __half g_wk[(size_t)NHEADS * DMODEL * DHEAD];
__device__ __align__(16) __half g_wv[(size_t)NHEADS * DMODEL * DHEAD];
__device__ __align__(16) __half g_wo[(size_t)DMODEL * DMODEL];
// attention operands [b][h][s][d]: Q split fp16, K/V single fp16
__device__ __align__(16) __half g_qhi[(size_t)BATCH * NHEADS * SEQ * DHEAD];
__device__ __align__(16) __half g_qlo[(size_t)BATCH * NHEADS * SEQ * DHEAD];
__device__ __align__(16) __half g_k  [(size_t)BATCH * NHEADS * SEQ * DHEAD];
__device__ __align__(16) __half g_v  [(size_t)BATCH * NHEADS * SEQ * DHEAD];
// attention output: fp16 hi/lo [b][s][h][d]
__device__ __align__(16) __half g_zhi[(size_t)BATCH * SEQ * NHEADS * DHEAD];
__device__ __align__(16) __half g_zlo[(size_t)BATCH * SEQ * NHEADS * DHEAD];

// ========================= helpers =========================================
__device__ __forceinline__ void ldsm_x4(uint32_t r[4], uint32_t addr) {
    asm volatile("ldmatrix.sync.aligned.m8n8.x4.shared.b16 {%0,%1,%2,%3}, [%4];"
                 : "=r"(r[0]), "=r"(r[1]), "=r"(r[2]), "=r"(r[3]) : "r"(addr));
}
__device__ __forceinline__ void ldsm_x4_t(uint32_t r[4], uint32_t addr) {
    asm volatile("ldmatrix.sync.aligned.m8n8.x4.trans.shared.b16 {%0,%1,%2,%3}, [%4];"
                 : "=r"(r[0]), "=r"(r[1]), "=r"(r[2]), "=r"(r[3]) : "r"(addr));
}
__device__ __forceinline__ void mma_f16(float c[4], const uint32_t a[4],
                                        uint32_t b0, uint32_t b1) {
    asm volatile("mma.sync.aligned.m16n8k16.row.col.f32.f16.f16.f32 "
                 "{%0,%1,%2,%3}, {%4,%5,%6,%7}, {%8,%9}, {%0,%1,%2,%3};"
                 : "+f"(c[0]), "+f"(c[1]), "+f"(c[2]), "+f"(c[3])
                 : "r"(a[0]), "r"(a[1]), "r"(a[2]), "r"(a[3]), "r"(b0), "r"(b1));
}
__device__ __forceinline__ uint32_t smem_to_u32(const void* p) {
    uint32_t a;
    asm("{ .reg .u64 t; cvta.to.shared.u64 t, %1; cvt.u32.u64 %0, t; }"
        : "=r"(a) : "l"(p));
    return a;
}
__device__ __forceinline__ uint32_t pack2h(__half lo, __half hi) {
    return (uint32_t)__half_as_ushort(lo) | ((uint32_t)__half_as_ushort(hi) << 16);
}
__device__ __forceinline__ void cp_async16(uint32_t dst, const void* src) {
    asm volatile("cp.async.cg.shared.global [%0], [%1], 16;" :: "r"(dst), "l"(src));
}
__device__ __forceinline__ void cp_commit() {
    asm volatile("cp.async.commit_group;" ::: "memory");
}
__device__ __forceinline__ void cp_wait0() {
    asm volatile("cp.async.wait_group 0;" ::: "memory");
}
__device__ __forceinline__ void cp_wait1() {
    asm volatile("cp.async.wait_group 1;" ::: "memory");
}
__device__ __forceinline__ void split2h(float f, __half& h, __half& l) {
    h = __float2half(f);
    l = __float2half(f - __half2float(h));
}

// ===================== conversion pre-pass (single launch) =================
__global__ __launch_bounds__(256) void convert_all(
    const float* __restrict__ resid,
    const float* __restrict__ WQ, const float* __restrict__ WK,
    const float* __restrict__ WV, const float* __restrict__ WO)
{
    const int which = blockIdx.y;
    int i = blockIdx.x * 256 + threadIdx.x;
    const float* src; __half* dst; int n4;
    switch (which) {
        case 0: src = resid; dst = g_r;  n4 = NTOK * DMODEL / 4; break;
        case 1: src = WQ;    dst = g_wq; n4 = NHEADS * DMODEL * DHEAD / 4; break;
        case 2: src = WK;    dst = g_wk; n4 = NHEADS * DMODEL * DHEAD / 4; break;
        case 3: src = WV;    dst = g_wv; n4 = NHEADS * DMODEL * DHEAD / 4; break;
        default:src = WO;    dst = g_wo; n4 = DMODEL * DMODEL / 4; break;
    }
    if (i >= n4) return;
    float4 v = reinterpret_cast<const float4*>(src)[i];
    reinterpret_cast<uint2*>(dst)[i] =
        make_uint2(pack2h(__float2half(v.x), __float2half(v.y)),
                   pack2h(__float2half(v.z), __float2half(v.w)));
}

// ===================== single-pass fp16 GEMM (qkv), KT=64 ==================
// 128x128 CTA tile, KT=64 k-step, 2-stage cp.async pipeline, 2 CTAs/SM.
// Stage (32KB): A [128 rows x 128B] @0, B [64 rows x 256B] @16384.
#define KT1    64
#define STG1   32768
#define SM_GEMM1 (2 * STG1)

__device__ __forceinline__ void gemm1_load_stage(
    uint32_t base, const __half* A, int lda,
    const __half* B, int ldb, int k0, int tid)
{
    #pragma unroll
    for (int it = 0; it < 4; it++) {             // A: 1024 chunks
        int idx = tid + it * 256;
        int m  = idx >> 3;
        int c8 = idx & 7;
        uint32_t d = base + (uint32_t)(m * 128 + ((c8 ^ (m & 7)) << 4));
        cp_async16(d, A + (size_t)m * lda + k0 + c8 * 8);
    }
    #pragma unroll
    for (int it = 0; it < 4; it++) {             // B: 1024 chunks
        int idx = tid + it * 256;
        int k  = idx >> 4;                       // 0..63
        int c8 = idx & 15;
        uint32_t d = base + 16384 + (uint32_t)(k * 256 + ((c8 ^ (k & 7)) << 4));
        cp_async16(d, B + (size_t)(k0 + k) * ldb + c8 * 8);
    }
}

__device__ __forceinline__ void gemm1_compute_stage(
    uint32_t base, int lane, int wm, int wn, float acc[4][4][4])
{
    #pragma unroll
    for (int k16 = 0; k16 < 4; k16++) {
        uint32_t bh[4][2];
        #pragma unroll
        for (int nf = 0; nf < 2; nf++) {
            int kk = k16 * 16 + (lane & 15);
            int nn = wn + nf * 16 + ((lane >> 4) << 3);
            uint32_t off = (uint32_t)(kk * 256 + (((nn >> 3) ^ (kk & 7)) << 4));
            uint32_t r[4];
            ldsm_x4_t(r, base + 16384 + off);
            bh[nf * 2][0] = r[0]; bh[nf * 2][1] = r[1];
            bh[nf * 2 + 1][0] = r[2]; bh[nf * 2 + 1][1] = r[3];
        }
        #pragma unroll
        for (int mi = 0; mi < 4; mi++) {
            int mm = wm + mi * 16 + (lane & 15);
            int c8 = k16 * 2 + (lane >> 4);      // 0..7
            uint32_t off = (uint32_t)(mm * 128 + ((c8 ^ (mm & 7)) << 4));
            uint32_t ah[4];
            ldsm_x4(ah, base + off);
            #pragma unroll
            for (int ni = 0; ni < 4; ni++)
                mma_f16(acc[mi][ni], ah, bh[ni][0], bh[ni][1]);
        }
    }
}

__device__ __forceinline__ void gemm1_mainloop(
    const __half* __restrict__ A, int lda,
    const __half* __restrict__ B, int ldb,
    char* smem, float acc[4][4][4])
{
    const int tid  = threadIdx.x;
    const int lane = tid & 31;
    const int wid  = tid >> 5;
    const int wm   = (wid >> 2) * 64;
    const int wn   = (wid & 3) * 32;
    const uint32_t sb = smem_to_u32(smem);
    const int NIT = DMODEL / KT1;                // 32

    gemm1_load_stage(sb, A, lda, B, ldb, 0, tid);
    cp_commit();

    for (int i = 0; i < NIT; i++) {
        if (i + 1 < NIT) {
            gemm1_load_stage(sb + ((i + 1) & 1) * STG1, A, lda, B, ldb,
                             (i + 1) * KT1, tid);
            cp_commit();
            cp_wait1();
        } else {
            cp_wait0();
        }
        __syncthreads();
        gemm1_compute_stage(sb + (i & 1) * STG1, lane, wm, wn, acc);
        __syncthreads();
    }
}

// ===================== 2-pass fp16 GEMM (o-proj), KT=32 ====================
#define KT2   32
#define STG2  24576
#define SM_GEMM2 (2 * STG2)

__device__ __forceinline__ void gemm2_load_stage(
    uint32_t base, const __half* Ahi, const __half* Alo, int lda,
    const __half* B, int ldb, int k0, int tid)
{
    #pragma unroll
    for (int it = 0; it < 4; it++) {
        int idx = tid + it * 256;
        int m  = idx >> 3;
        int c8 = idx & 7;
        uint32_t d = base + (uint32_t)(m * 128 + ((c8 ^ (m & 7)) << 4));
        const __half* s = (c8 < 4) ? (Ahi + (size_t)m * lda + k0 + c8 * 8)
                                   : (Alo + (size_t)m * lda + k0 + (c8 - 4) * 8);
        cp_async16(d, s);
    }
    #pragma unroll
    for (int it = 0; it < 2; it++) {
        int idx = tid + it * 256;
        int k  = idx >> 4;
        int c8 = idx & 15;
        uint32_t d = base + 16384 + (uint32_t)(k * 256 + ((c8 ^ (k & 7)) << 4));
        cp_async16(d, B + (size_t)(k0 + k) * ldb + c8 * 8);
    }
}

__device__ __forceinline__ void gemm2_compute_stage(
    uint32_t base, int lane, int wm, int wn, float acc[4][4][4])
{
    #pragma unroll
    for (int k16 = 0; k16 < 2; k16++) {
        uint32_t bh[4][2];
        #pragma unroll
        for (int nf = 0; nf < 2; nf++) {
            int kk = k16 * 16 + (lane & 15);
            int nn = wn + nf * 16 + ((lane >> 4) << 3);
            uint32_t off = (uint32_t)(kk * 256 + (((nn >> 3) ^ (kk & 7)) << 4));
            uint32_t r[4];
            ldsm_x4_t(r, base + 16384 + off);
            bh[nf * 2][0] = r[0]; bh[nf * 2][1] = r[1];
            bh[nf * 2 + 1][0] = r[2]; bh[nf * 2 + 1][1] = r[3];
        }
        #pragma unroll
        for (int mi = 0; mi < 4; mi++) {
            int mm = wm + mi * 16 + (lane & 15);
            int c8 = k16 * 2 + (lane >> 4);
            uint32_t oh = (uint32_t)(mm * 128 + ((c8 ^ (mm & 7)) << 4));
            uint32_t ol = (uint32_t)(mm * 128 + (((c8 | 4) ^ (mm & 7)) << 4));
            uint32_t ah[4], al[4];
            ldsm_x4(ah, base + oh);
            ldsm_x4(al, base + ol);
            #pragma unroll
            for (int ni = 0; ni < 4; ni++) {
                mma_f16(acc[mi][ni], ah, bh[ni][0], bh[ni][1]);
                mma_f16(acc[mi][ni], al, bh[ni][0], bh[ni][1]);
            }
        }
    }
}

__device__ __forceinline__ void gemm2_mainloop(
    const __half* __restrict__ Ahi, const __half* __restrict__ Alo, int lda,
    const __half* __restrict__ B, int ldb,
    char* smem, float acc[4][4][4])
{
    const int tid  = threadIdx.x;
    const int lane = tid & 31;
    const int wid  = tid >> 5;
    const int wm   = (wid >> 2) * 64;
    const int wn   = (wid & 3) * 32;
    const uint32_t sb = smem_to_u32(smem);
    const int NIT = DMODEL / KT2;

    gemm2_load_stage(sb, Ahi, Alo, lda, B, ldb, 0, tid);
    cp_commit();

    for (int i = 0; i < NIT; i++) {
        if (i + 1 < NIT) {
            gemm2_load_stage(sb + ((i + 1) & 1) * STG2, Ahi, Alo, lda,
                             B, ldb, (i + 1) * KT2, tid);
            cp_commit();
            cp_wait1();
        } else {
            cp_wait0();
        }
        __syncthreads();
        gemm2_compute_stage(sb + (i & 1) * STG2, lane, wm, wn, acc);
        __syncthreads();
    }
}

// ----------------------- QKV projection (single-pass fp16) -----------------
__global__ __launch_bounds__(256, 2) void qkv_tc(
    const float* __restrict__ bQ, const float* __restrict__ bK,
    const float* __restrict__ bV)
{
    extern __shared__ char smem[];
    const int i0 = blockIdx.x * 128;
    const int h  = blockIdx.y;
    const int which = blockIdx.z;

    const __half* W   = (which == 0) ? g_wq : (which == 1) ? g_wk : g_wv;
    const float* bias = (which == 0) ? bQ : (which == 1) ? bK : bV;

    float acc[4][4][4];
    #pragma unroll
    for (int mi = 0; mi < 4; mi++)
        #pragma unroll
        for (int ni = 0; ni < 4; ni++)
            #pragma unroll
            for (int j = 0; j < 4; j++) acc[mi][ni][j] = 0.0f;

    gemm1_mainloop(g_r + (size_t)i0 * DMODEL, DMODEL,
                   W + (size_t)h * DMODEL * DHEAD, DHEAD, smem, acc);

    const int lane = threadIdx.x & 31;
    const int wid  = threadIdx.x >> 5;
    const int wm   = (wid >> 2) * 64;
    const int wn   = (wid & 3) * 32;
    #pragma unroll
    for (int mi = 0; mi < 4; mi++) {
        #pragma unroll
        for (int ni = 0; ni < 4; ni++) {
            int col = wn + ni * 8 + (lane & 3) * 2;
            float b0 = bias[h * DHEAD + col];
            float b1 = bias[h * DHEAD + col + 1];
            #pragma unroll
            for (int half = 0; half < 2; half++) {
                int i = i0 + wm + mi * 16 + (lane >> 2) + half * 8;
                int bb = i >> 11, s = i & 2047;
                size_t base = (((size_t)bb * NHEADS + h) * SEQ + s) * DHEAD + col;
                float f0 = acc[mi][ni][half * 2] + b0;
                float f1 = acc[mi][ni][half * 2 + 1] + b1;
                if (which == 0) {
                    __half h0, h1, l0, l1;
                    split2h(f0, h0, l0); split2h(f1, h1, l1);
                    *reinterpret_cast<uint32_t*>(&g_qhi[base]) = pack2h(h0, h1);
                    *reinterpret_cast<uint32_t*>(&g_qlo[base]) = pack2h(l0, l1);
                } else {
                    __half* dst = (which == 1) ? g_k : g_v;
                    *reinterpret_cast<uint32_t*>(&dst[base]) =
                        pack2h(__float2half(f0), __float2half(f1));
                }
            }
        }
    }
}

// ----------------------- Output projection (2-pass fp16) -------------------
__global__ __launch_bounds__(256, 2) void o_tc(
    const float* __restrict__ bO, float* __restrict__ out)
{
    extern __shared__ char smem[];
    const int i0 = blockIdx.x * 128;
    const int j0 = blockIdx.y * 128;

    float acc[4][4][4];
    #pragma unroll
    for (int mi = 0; mi < 4; mi++)
        #pragma unroll
        for (int ni = 0; ni < 4; ni++)
            #pragma unroll
            for (int j = 0; j < 4; j++) acc[mi][ni][j] = 0.0f;

    gemm2_mainloop(g_zhi + (size_t)i0 * DMODEL, g_zlo + (size_t)i0 * DMODEL, DMODEL,
                   g_wo + j0, DMODEL, smem, acc);

    const int lane = threadIdx.x & 31;
    const int wid  = threadIdx.x >> 5;
    const int wm   = (wid >> 2) * 64;
    const int wn   = (wid & 3) * 32;
    #pragma unroll
    for (int mi = 0; mi < 4; mi++) {
        #pragma unroll
        for (int ni = 0; ni < 4; ni++) {
            int col = j0 + wn + ni * 8 + (lane & 3) * 2;
            float b0 = bO[col], b1 = bO[col + 1];
            #pragma unroll
            for (int half = 0; half < 2; half++) {
                int i = i0 + wm + mi * 16 + (lane >> 2) + half * 8;
                float2 v = make_float2(acc[mi][ni][half * 2] + b0,
                                       acc[mi][ni][half * 2 + 1] + b1);
                *reinterpret_cast<float2*>(out + (size_t)i * DMODEL + col) = v;
            }
        }
    }
}

// ---------------------------------------------------------------------------
// Causal flash attention, fp16 2-pass both GEMMs (unchanged R10).
// Stage (32KB): K @0 (16KB), V @16384. 2 stages = 64KB.
// ---------------------------------------------------------------------------
#define BQ2 128
#define BK2 64
#define ATSTG 32768
#define AT_SMEM (2 * ATSTG)

__device__ __forceinline__ void attn_load_kv(
    uint32_t base, const __half* Kg, const __half* Vg, int k0, int tid)
{
    #pragma unroll
    for (int it = 0; it < 4; it++) {
        int idx = tid + it * 256;                // 0..1023
        int r  = idx >> 4;
        int c8 = idx & 15;
        uint32_t d = (uint32_t)(r * 256 + ((c8 ^ (r & 7)) << 4));
        size_t so = (size_t)(k0 + r) * DHEAD + c8 * 8;
        cp_async16(base + d,         Kg + so);
        cp_async16(base + 16384 + d, Vg + so);
    }
}

__global__ __launch_bounds__(256, 1) void attn_tc()
{
    extern __shared__ char smem[];
    const uint32_t sb = smem_to_u32(smem);
    const int tid  = threadIdx.x;
    const int lane = tid & 31;
    const int w    = tid >> 5;
    const int q0   = blockIdx.x * BQ2;
    const int h    = blockIdx.y;
    const int b    = blockIdx.z;

    const size_t head_off = ((size_t)b * NHEADS + h) * SEQ * DHEAD;
    const __half* Qhig = g_qhi + head_off + (size_t)q0 * DHEAD;
    const __half* Qlog = g_qlo + head_off + (size_t)q0 * DHEAD;
    const __half* Kg   = g_k   + head_off;
    const __half* Vg   = g_v   + head_off;

    const int NIT = (q0 + BQ2) / BK2;

    // ---- Q prologue
    #pragma unroll
    for (int it = 0; it < 8; it++) {
        int idx = tid + it * 256;
        int m  = idx >> 4;
        int c8 = idx & 15;
        uint32_t d = (uint32_t)(m * 256 + ((c8 ^ (m & 7)) << 4));
        size_t so = (size_t)m * DHEAD + c8 * 8;
        cp_async16(sb + d,         Qhig + so);
        cp_async16(sb + ATSTG + d, Qlog + so);
    }
    cp_commit();
    cp_wait0();
    __syncthreads();

    uint32_t qh[8][4], ql[8][4];
    #pragma unroll
    for (int t = 0; t < 8; t++) {
        int row = w * 16 + (lane & 15);
        int col = t * 16 + ((lane >> 4) << 3);
        uint32_t off = (uint32_t)(row * 256 + (((col >> 3) ^ (row & 7)) << 4));
        ldsm_x4(qh[t], sb + off);
        ldsm_x4(ql[t], sb + ATSTG + off);
    }
    __syncthreads();

    attn_load_kv(sb, Kg, Vg, 0, tid);
    cp_commit();

    float O[16][4];
    #pragma unroll
    for (int nf = 0; nf < 16; nf++)
        #pragma unroll
        for (int j = 0; j < 4; j++) O[nf][j] = 0.0f;
    float m0 = -INFINITY, m1 = -INFINITY, l0 = 0.0f, l1 = 0.0f;

    const float sc_scale = 0.08838834764831843f;
    const int rbase = q0 + w * 16;

    for (int i = 0; i < NIT; i++) {
        const int k0 = i * BK2;
        if (i + 1 < NIT) {
            attn_load_kv(sb + ((i + 1) & 1) * ATSTG, Kg, Vg, (i + 1) * BK2, tid);
            cp_commit();
            cp_wait1();
        } else {
            cp_wait0();
        }
        __syncthreads();
        const uint32_t base = sb + (i & 1) * ATSTG;

        // ---- S = Q K^T (fp16 2-pass)
        float sf[8][4];
        #pragma unroll
        for (int nf = 0; nf < 8; nf++)
            #pragma unroll
            for (int j = 0; j < 4; j++) sf[nf][j] = 0.0f;

        #pragma unroll
        for (int t = 0; t < 8; t++) {
            #pragma unroll
            for (int nb = 0; nb < 4; nb++) {
                int row = nb * 16 + (lane & 15);
                int col = t * 16 + ((lane >> 4) << 3);
                uint32_t off = (uint32_t)(row * 256 + (((col >> 3) ^ (row & 7)) << 4));
                uint32_t kh[4];
                ldsm_x4(kh, base + off);
                mma_f16(sf[2 * nb],     qh[t], kh[0], kh[2]);
                mma_f16(sf[2 * nb],     ql[t], kh[0], kh[2]);
                mma_f16(sf[2 * nb + 1], qh[t], kh[1], kh[3]);
                mma_f16(sf[2 * nb + 1], ql[t], kh[1], kh[3]);
            }
        }

        // ---- scale + causal mask
        const bool need_mask = (k0 + BK2 - 1) > (rbase);
        #pragma unroll
        for (int nf = 0; nf < 8; nf++)
            #pragma unroll
            for (int j = 0; j < 4; j++) {
                float s = sf[nf][j] * sc_scale;
                if (need_mask) {
                    int col = k0 + nf * 8 + (lane & 3) * 2 + (j & 1);
                    int row = rbase + (lane >> 2) + (j >> 1) * 8;
                    if (col > row) s = -INFINITY;
                }
                sf[nf][j] = s;
            }

        // ---- online softmax
        float mx0 = -INFINITY, mx1 = -INFINITY;
        #pragma unroll
        for (int nf = 0; nf < 8; nf++) {
            mx0 = fmaxf(mx0, fmaxf(sf[nf][0], sf[nf][1]));
            mx1 = fmaxf(mx1, fmaxf(sf[nf][2], sf[nf][3]));
        }
        mx0 = fmaxf(mx0, __shfl_xor_sync(0xffffffffu, mx0, 1));
        mx0 = fmaxf(mx0, __shfl_xor_sync(0xffffffffu, mx0, 2));
        mx1 = fmaxf(mx1, __shfl_xor_sync(0xffffffffu, mx1, 1));
        mx1 = fmaxf(mx1, __shfl_xor_sync(0xffffffffu, mx1, 2));

        float mn0 = fmaxf(m0, mx0), mn1 = fmaxf(m1, mx1);
        float cr0 = __expf(m0 - mn0), cr1 = __expf(m1 - mn1);

        float sum0 = 0.0f, sum1 = 0.0f;
        #pragma unroll
        for (int nf = 0; nf < 8; nf++) {
            float p0 = __expf(sf[nf][0] - mn0);
            float p1 = __expf(sf[nf][1] - mn0);
            float p2 = __expf(sf[nf][2] - mn1);
            float p3 = __expf(sf[nf][3] - mn1);
            sf[nf][0] = p0; sf[nf][1] = p1; sf[nf][2] = p2; sf[nf][3] = p3;
            sum0 += p0 + p1; sum1 += p2 + p3;
        }
        sum0 += __shfl_xor_sync(0xffffffffu, sum0, 1);
        sum0 += __shfl_xor_sync(0xffffffffu, sum0, 2);
        sum1 += __shfl_xor_sync(0xffffffffu, sum1, 1);
        sum1 += __shfl_xor_sync(0xffffffffu, sum1, 2);
        l0 = l0 * cr0 + sum0;  l1 = l1 * cr1 + sum1;
        m0 = mn0;  m1 = mn1;

        #pragma unroll
        for (int nf = 0; nf < 16; nf++) {
            O[nf][0] *= cr0; O[nf][1] *= cr0;
            O[nf][2] *= cr1; O[nf][3] *= cr1;
        }

        // ---- P -> A frags (fp16 hi + residual lo)
        uint32_t pa[4][4], pl[4][4];
        #pragma unroll
        for (int kb = 0; kb < 4; kb++) {
            #pragma unroll
            for (int half = 0; half < 2; half++) {
                #pragma unroll
                for (int rr = 0; rr < 2; rr++) {
                    float f0 = sf[2 * kb + half][rr * 2];
                    float f1 = sf[2 * kb + half][rr * 2 + 1];
                    __half h0, h1, e0, e1;
                    split2h(f0, h0, e0); split2h(f1, h1, e1);
                    pa[kb][half * 2 + rr] = pack2h(h0, h1);
                    pl[kb][half * 2 + rr] = pack2h(e0, e1);
                }
            }
        }

        // ---- O += P V (fp16 2-pass)
        #pragma unroll
        for (int kb = 0; kb < 4; kb++) {
            #pragma unroll
            for (int nf2 = 0; nf2 < 8; nf2++) {
                int kk = kb * 16 + (lane & 15);
                int nn = nf2 * 16 + ((lane >> 4) << 3);
                uint32_t off = (uint32_t)(kk * 256 + (((nn >> 3) ^ (kk & 7)) << 4));
                uint32_t vh[4];
                ldsm_x4_t(vh, base + 16384 + off);
                mma_f16(O[2 * nf2],     pa[kb], vh[0], vh[1]);
                mma_f16(O[2 * nf2],     pl[kb], vh[0], vh[1]);
                mma_f16(O[2 * nf2 + 1], pa[kb], vh[2], vh[3]);
                mma_f16(O[2 * nf2 + 1], pl[kb], vh[2], vh[3]);
            }
        }
        __syncthreads();
    }

    // ---- normalize + write z (fp16 hi/lo split) [b][s][h][d]
    float inv0 = 1.0f / l0, inv1 = 1.0f / l1;
    int r0 = rbase + (lane >> 2);
    size_t z0 = (((size_t)b * SEQ + r0) * NHEADS + h) * DHEAD;
    size_t z1 = (((size_t)b * SEQ + r0 + 8) * NHEADS + h) * DHEAD;
    #pragma unroll
    for (int nf = 0; nf < 16; nf++) {
        int col = nf * 8 + (lane & 3) * 2;
        __half h0, h1, e0, e1;
        split2h(O[nf][0] * inv0, h0, e0);
        split2h(O[nf][1] * inv0, h1, e1);
        *reinterpret_cast<uint32_t*>(&g_zhi[z0 + col]) = pack2h(h0, h1);
        *reinterpret_cast<uint32_t*>(&g_zlo[z0 + col]) = pack2h(e0, e1);
        split2h(O[nf][2] * inv1, h0, e0);
        split2h(O[nf][3] * inv1, h1, e1);
        *reinterpret_cast<uint32_t*>(&g_zhi[z1 + col]) = pack2h(h0, h1);
        *reinterpret_cast<uint32_t*>(&g_zlo[z1 + col]) = pack2h(e0, e1);
    }
}

// ---------------------------------------------------------------------------
extern "C" void kernel_launch(void* const* d_in, const int* in_sizes, int n_in,
                              void* d_out, int out_size)
{
    (void)in_sizes; (void)n_in; (void)out_size;
    const float* residual = (const float*)d_in[0];
    const float* WQ = (const float*)d_in[2];
    const float* WK = (const float*)d_in[3];
    const float* WV = (const float*)d_in[4];
    const float* WO = (const float*)d_in[5];
    const float* bQ = (const float*)d_in[6];
    const float* bK = (const float*)d_in[7];
    const float* bV = (const float*)d_in[8];
    const float* bO = (const float*)d_in[9];
    float* out = (float*)d_out;

    // tuple element 0: residual pass-through
    cudaMemcpyAsync(out, residual, (size_t)BATCH * SEQ * DMODEL * sizeof(float),
                    cudaMemcpyDeviceToDevice);

    // single fused conversion pre-pass
    dim3 gc(NTOK * DMODEL / 4 / 256, 5);
    convert_all<<<gc, 256>>>(residual, WQ, WK, WV, WO);

    cudaFuncSetAttribute(qkv_tc,  cudaFuncAttributeMaxDynamicSharedMemorySize, SM_GEMM1);
    cudaFuncSetAttribute(o_tc,    cudaFuncAttributeMaxDynamicSharedMemorySize, SM_GEMM2);
    cudaFuncSetAttribute(attn_tc, cudaFuncAttributeMaxDynamicSharedMemorySize, AT_SMEM);

    dim3 g1(NTOK / 128, NHEADS, 3);
    qkv_tc<<<g1, 256, SM_GEMM1>>>(bQ, bK, bV);

    dim3 g2(SEQ / BQ2, NHEADS, BATCH);
    attn_tc<<<g2, 256, AT_SMEM>>>();

    dim3 g3(NTOK / 128, DMODEL / 128);
    o_tc<<<g3, 256, SM_GEMM2>>>(bO, out + (size_t)BATCH * SEQ * DMODEL);
}

// round 12
// speedup vs baseline: 2.3816x; 1.2495x over previous
#include <cuda_runtime.h>
#include <cuda_bf16.h>
#include <cuda_fp16.h>
#include <math.h>
#include <stdint.h>

#define BATCH   2
#define SEQ     2048
#define DMODEL  2048
#define NHEADS  16
#define DHEAD   128
#define NTOK    (BATCH * SEQ)      // 4096

// ---------------- scratch (device globals; no allocation allowed) ----------
__device__ __align__(16) __half g_r[(size_t)NTOK * DMODEL];        // residual fp16
__device__ __align__(16) __half g_wq[(size_t)NHEADS * DMODEL * DHEAD];
__device__ __align__(16) __half g_wk[(size_t)NHEADS * DMODEL * DHEAD];
__device__ __align__(16) __half g_wv[(size_t)NHEADS * DMODEL * DHEAD];
__device__ __align__(16) __half g_wo[(size_t)DMODEL * DMODEL];
// attention operands [b][h][s][d]: Q split fp16 (protect logits), K/V single fp16
__device__ __align__(16) __half g_qhi[(size_t)BATCH * NHEADS * SEQ * DHEAD];
__device__ __align__(16) __half g_qlo[(size_t)BATCH * NHEADS * SEQ * DHEAD];
__device__ __align__(16) __half g_k  [(size_t)BATCH * NHEADS * SEQ * DHEAD];
__device__ __align__(16) __half g_v  [(size_t)BATCH * NHEADS * SEQ * DHEAD];
// attention output: single fp16 [b][s][h][d]
__device__ __align__(16) __half g_z  [(size_t)BATCH * SEQ * NHEADS * DHEAD];

// ========================= helpers =========================================
__device__ __forceinline__ void ldsm_x4(uint32_t r[4], uint32_t addr) {
    asm volatile("ldmatrix.sync.aligned.m8n8.x4.shared.b16 {%0,%1,%2,%3}, [%4];"
                 : "=r"(r[0]), "=r"(r[1]), "=r"(r[2]), "=r"(r[3]) : "r"(addr));
}
__device__ __forceinline__ void ldsm_x4_t(uint32_t r[4], uint32_t addr) {
    asm volatile("ldmatrix.sync.aligned.m8n8.x4.trans.shared.b16 {%0,%1,%2,%3}, [%4];"
                 : "=r"(r[0]), "=r"(r[1]), "=r"(r[2]), "=r"(r[3]) : "r"(addr));
}
__device__ __forceinline__ void mma_f16(float c[4], const uint32_t a[4],
                                        uint32_t b0, uint32_t b1) {
    asm volatile("mma.sync.aligned.m16n8k16.row.col.f32.f16.f16.f32 "
                 "{%0,%1,%2,%3}, {%4,%5,%6,%7}, {%8,%9}, {%0,%1,%2,%3};"
                 : "+f"(c[0]), "+f"(c[1]), "+f"(c[2]), "+f"(c[3])
                 : "r"(a[0]), "r"(a[1]), "r"(a[2]), "r"(a[3]), "r"(b0), "r"(b1));
}
__device__ __forceinline__ uint32_t smem_to_u32(const void* p) {
    uint32_t a;
    asm("{ .reg .u64 t; cvta.to.shared.u64 t, %1; cvt.u32.u64 %0, t; }"
        : "=r"(a) : "l"(p));
    return a;
}
__device__ __forceinline__ uint32_t pack2h(__half lo, __half hi) {
    return (uint32_t)__half_as_ushort(lo) | ((uint32_t)__half_as_ushort(hi) << 16);
}
__device__ __forceinline__ void cp_async16(uint32_t dst, const void* src) {
    asm volatile("cp.async.cg.shared.global [%0], [%1], 16;" :: "r"(dst), "l"(src));
}
__device__ __forceinline__ void cp_commit() {
    asm volatile("cp.async.commit_group;" ::: "memory");
}
__device__ __forceinline__ void cp_wait0() {
    asm volatile("cp.async.wait_group 0;" ::: "memory");
}
__device__ __forceinline__ void cp_wait1() {
    asm volatile("cp.async.wait_group 1;" ::: "memory");
}
__device__ __forceinline__ void split2h(float f, __half& h, __half& l) {
    h = __float2half(f);
    l = __float2half(f - __half2float(h));
}

// ===================== conversion pre-pass (single launch) =================
__global__ __launch_bounds__(256) void convert_all(
    const float* __restrict__ resid,
    const float* __restrict__ WQ, const float* __restrict__ WK,
    const float* __restrict__ WV, const float* __restrict__ WO)
{
    const int which = blockIdx.y;
    int i = blockIdx.x * 256 + threadIdx.x;
    const float* src; __half* dst; int n4;
    switch (which) {
        case 0: src = resid; dst = g_r;  n4 = NTOK * DMODEL / 4; break;
        case 1: src = WQ;    dst = g_wq; n4 = NHEADS * DMODEL * DHEAD / 4; break;
        case 2: src = WK;    dst = g_wk; n4 = NHEADS * DMODEL * DHEAD / 4; break;
        case 3: src = WV;    dst = g_wv; n4 = NHEADS * DMODEL * DHEAD / 4; break;
        default:src = WO;    dst = g_wo; n4 = DMODEL * DMODEL / 4; break;
    }
    if (i >= n4) return;
    float4 v = reinterpret_cast<const float4*>(src)[i];
    reinterpret_cast<uint2*>(dst)[i] =
        make_uint2(pack2h(__float2half(v.x), __float2half(v.y)),
                   pack2h(__float2half(v.z), __float2half(v.w)));
}

// ===================== single-pass fp16 GEMM, KT=64 ========================
// 128x128 CTA tile, KT=64 k-step, 2-stage cp.async pipeline, 2 CTAs/SM.
// Stage (32KB): A [128 rows x 128B] @0, B [64 rows x 256B] @16384.
#define KT1    64
#define STG1   32768
#define SM_GEMM1 (2 * STG1)

__device__ __forceinline__ void gemm1_load_stage(
    uint32_t base, const __half* A, int lda,
    const __half* B, int ldb, int k0, int tid)
{
    #pragma unroll
    for (int it = 0; it < 4; it++) {             // A: 1024 chunks
        int idx = tid + it * 256;
        int m  = idx >> 3;
        int c8 = idx & 7;
        uint32_t d = base + (uint32_t)(m * 128 + ((c8 ^ (m & 7)) << 4));
        cp_async16(d, A + (size_t)m * lda + k0 + c8 * 8);
    }
    #pragma unroll
    for (int it = 0; it < 4; it++) {             // B: 1024 chunks
        int idx = tid + it * 256;
        int k  = idx >> 4;                       // 0..63
        int c8 = idx & 15;
        uint32_t d = base + 16384 + (uint32_t)(k * 256 + ((c8 ^ (k & 7)) << 4));
        cp_async16(d, B + (size_t)(k0 + k) * ldb + c8 * 8);
    }
}

__device__ __forceinline__ void gemm1_compute_stage(
    uint32_t base, int lane, int wm, int wn, float acc[4][4][4])
{
    #pragma unroll
    for (int k16 = 0; k16 < 4; k16++) {
        uint32_t bh[4][2];
        #pragma unroll
        for (int nf = 0; nf < 2; nf++) {
            int kk = k16 * 16 + (lane & 15);
            int nn = wn + nf * 16 + ((lane >> 4) << 3);
            uint32_t off = (uint32_t)(kk * 256 + (((nn >> 3) ^ (kk & 7)) << 4));
            uint32_t r[4];
            ldsm_x4_t(r, base + 16384 + off);
            bh[nf * 2][0] = r[0]; bh[nf * 2][1] = r[1];
            bh[nf * 2 + 1][0] = r[2]; bh[nf * 2 + 1][1] = r[3];
        }
        #pragma unroll
        for (int mi = 0; mi < 4; mi++) {
            int mm = wm + mi * 16 + (lane & 15);
            int c8 = k16 * 2 + (lane >> 4);      // 0..7
            uint32_t off = (uint32_t)(mm * 128 + ((c8 ^ (mm & 7)) << 4));
            uint32_t ah[4];
            ldsm_x4(ah, base + off);
            #pragma unroll
            for (int ni = 0; ni < 4; ni++)
                mma_f16(acc[mi][ni], ah, bh[ni][0], bh[ni][1]);
        }
    }
}

__device__ __forceinline__ void gemm1_mainloop(
    const __half* __restrict__ A, int lda,
    const __half* __restrict__ B, int ldb,
    char* smem, float acc[4][4][4])
{
    const int tid  = threadIdx.x;
    const int lane = tid & 31;
    const int wid  = tid >> 5;
    const int wm   = (wid >> 2) * 64;
    const int wn   = (wid & 3) * 32;
    const uint32_t sb = smem_to_u32(smem);
    const int NIT = DMODEL / KT1;                // 32

    gemm1_load_stage(sb, A, lda, B, ldb, 0, tid);
    cp_commit();

    for (int i = 0; i < NIT; i++) {
        if (i + 1 < NIT) {
            gemm1_load_stage(sb + ((i + 1) & 1) * STG1, A, lda, B, ldb,
                             (i + 1) * KT1, tid);
            cp_commit();
            cp_wait1();
        } else {
            cp_wait0();
        }
        __syncthreads();
        gemm1_compute_stage(sb + (i & 1) * STG1, lane, wm, wn, acc);
        __syncthreads();
    }
}

// ----------------------- QKV projection (single-pass fp16) -----------------
__global__ __launch_bounds__(256, 2) void qkv_tc(
    const float* __restrict__ bQ, const float* __restrict__ bK,
    const float* __restrict__ bV)
{
    extern __shared__ char smem[];
    const int i0 = blockIdx.x * 128;
    const int h  = blockIdx.y;
    const int which = blockIdx.z;

    const __half* W   = (which == 0) ? g_wq : (which == 1) ? g_wk : g_wv;
    const float* bias = (which == 0) ? bQ : (which == 1) ? bK : bV;

    float acc[4][4][4];
    #pragma unroll
    for (int mi = 0; mi < 4; mi++)
        #pragma unroll
        for (int ni = 0; ni < 4; ni++)
            #pragma unroll
            for (int j = 0; j < 4; j++) acc[mi][ni][j] = 0.0f;

    gemm1_mainloop(g_r + (size_t)i0 * DMODEL, DMODEL,
                   W + (size_t)h * DMODEL * DHEAD, DHEAD, smem, acc);

    const int lane = threadIdx.x & 31;
    const int wid  = threadIdx.x >> 5;
    const int wm   = (wid >> 2) * 64;
    const int wn   = (wid & 3) * 32;
    #pragma unroll
    for (int mi = 0; mi < 4; mi++) {
        #pragma unroll
        for (int ni = 0; ni < 4; ni++) {
            int col = wn + ni * 8 + (lane & 3) * 2;
            float b0 = bias[h * DHEAD + col];
            float b1 = bias[h * DHEAD + col + 1];
            #pragma unroll
            for (int half = 0; half < 2; half++) {
                int i = i0 + wm + mi * 16 + (lane >> 2) + half * 8;
                int bb = i >> 11, s = i & 2047;
                size_t base = (((size_t)bb * NHEADS + h) * SEQ + s) * DHEAD + col;
                float f0 = acc[mi][ni][half * 2] + b0;
                float f1 = acc[mi][ni][half * 2 + 1] + b1;
                if (which == 0) {
                    __half h0, h1, l0, l1;
                    split2h(f0, h0, l0); split2h(f1, h1, l1);
                    *reinterpret_cast<uint32_t*>(&g_qhi[base]) = pack2h(h0, h1);
                    *reinterpret_cast<uint32_t*>(&g_qlo[base]) = pack2h(l0, l1);
                } else {
                    __half* dst = (which == 1) ? g_k : g_v;
                    *reinterpret_cast<uint32_t*>(&dst[base]) =
                        pack2h(__float2half(f0), __float2half(f1));
                }
            }
        }
    }
}

// ----------------------- Output projection (single-pass fp16) --------------
__global__ __launch_bounds__(256, 2) void o_tc(
    const float* __restrict__ bO, float* __restrict__ out)
{
    extern __shared__ char smem[];
    const int i0 = blockIdx.x * 128;
    const int j0 = blockIdx.y * 128;

    float acc[4][4][4];
    #pragma unroll
    for (int mi = 0; mi < 4; mi++)
        #pragma unroll
        for (int ni = 0; ni < 4; ni++)
            #pragma unroll
            for (int j = 0; j < 4; j++) acc[mi][ni][j] = 0.0f;

    gemm1_mainloop(g_z + (size_t)i0 * DMODEL, DMODEL, g_wo + j0, DMODEL, smem, acc);

    const int lane = threadIdx.x & 31;
    const int wid  = threadIdx.x >> 5;
    const int wm   = (wid >> 2) * 64;
    const int wn   = (wid & 3) * 32;
    #pragma unroll
    for (int mi = 0; mi < 4; mi++) {
        #pragma unroll
        for (int ni = 0; ni < 4; ni++) {
            int col = j0 + wn + ni * 8 + (lane & 3) * 2;
            float b0 = bO[col], b1 = bO[col + 1];
            #pragma unroll
            for (int half = 0; half < 2; half++) {
                int i = i0 + wm + mi * 16 + (lane >> 2) + half * 8;
                float2 v = make_float2(acc[mi][ni][half * 2] + b0,
                                       acc[mi][ni][half * 2 + 1] + b1);
                *reinterpret_cast<float2*>(out + (size_t)i * DMODEL + col) = v;
            }
        }
    }
}

// ---------------------------------------------------------------------------
// Causal flash attention: QK 2-pass (Q split), PV single-pass (P fp16).
// Stage (32KB): K @0 (16KB), V @16384. 2 stages = 64KB.
// ---------------------------------------------------------------------------
#define BQ2 128
#define BK2 64
#define ATSTG 32768
#define AT_SMEM (2 * ATSTG)

__device__ __forceinline__ void attn_load_kv(
    uint32_t base, const __half* Kg, const __half* Vg, int k0, int tid)
{
    #pragma unroll
    for (int it = 0; it < 4; it++) {
        int idx = tid + it * 256;                // 0..1023
        int r  = idx >> 4;
        int c8 = idx & 15;
        uint32_t d = (uint32_t)(r * 256 + ((c8 ^ (r & 7)) << 4));
        size_t so = (size_t)(k0 + r) * DHEAD + c8 * 8;
        cp_async16(base + d,         Kg + so);
        cp_async16(base + 16384 + d, Vg + so);
    }
}

__global__ __launch_bounds__(256, 1) void attn_tc()
{
    extern __shared__ char smem[];
    const uint32_t sb = smem_to_u32(smem);
    const int tid  = threadIdx.x;
    const int lane = tid & 31;
    const int w    = tid >> 5;
    const int q0   = blockIdx.x * BQ2;
    const int h    = blockIdx.y;
    const int b    = blockIdx.z;

    const size_t head_off = ((size_t)b * NHEADS + h) * SEQ * DHEAD;
    const __half* Qhig = g_qhi + head_off + (size_t)q0 * DHEAD;
    const __half* Qlog = g_qlo + head_off + (size_t)q0 * DHEAD;
    const __half* Kg   = g_k   + head_off;
    const __half* Vg   = g_v   + head_off;

    const int NIT = (q0 + BQ2) / BK2;

    // ---- Q prologue
    #pragma unroll
    for (int it = 0; it < 8; it++) {
        int idx = tid + it * 256;
        int m  = idx >> 4;
        int c8 = idx & 15;
        uint32_t d = (uint32_t)(m * 256 + ((c8 ^ (m & 7)) << 4));
        size_t so = (size_t)m * DHEAD + c8 * 8;
        cp_async16(sb + d,         Qhig + so);
        cp_async16(sb + ATSTG + d, Qlog + so);
    }
    cp_commit();
    cp_wait0();
    __syncthreads();

    uint32_t qh[8][4], ql[8][4];
    #pragma unroll
    for (int t = 0; t < 8; t++) {
        int row = w * 16 + (lane & 15);
        int col = t * 16 + ((lane >> 4) << 3);
        uint32_t off = (uint32_t)(row * 256 + (((col >> 3) ^ (row & 7)) << 4));
        ldsm_x4(qh[t], sb + off);
        ldsm_x4(ql[t], sb + ATSTG + off);
    }
    __syncthreads();

    attn_load_kv(sb, Kg, Vg, 0, tid);
    cp_commit();

    float O[16][4];
    #pragma unroll
    for (int nf = 0; nf < 16; nf++)
        #pragma unroll
        for (int j = 0; j < 4; j++) O[nf][j] = 0.0f;
    float m0 = -INFINITY, m1 = -INFINITY, l0 = 0.0f, l1 = 0.0f;

    const float sc_scale = 0.08838834764831843f;
    const int rbase = q0 + w * 16;

    for (int i = 0; i < NIT; i++) {
        const int k0 = i * BK2;
        if (i + 1 < NIT) {
            attn_load_kv(sb + ((i + 1) & 1) * ATSTG, Kg, Vg, (i + 1) * BK2, tid);
            cp_commit();
            cp_wait1();
        } else {
            cp_wait0();
        }
        __syncthreads();
        const uint32_t base = sb + (i & 1) * ATSTG;

        // ---- S = Q K^T (fp16 2-pass, Q split)
        float sf[8][4];
        #pragma unroll
        for (int nf = 0; nf < 8; nf++)
            #pragma unroll
            for (int j = 0; j < 4; j++) sf[nf][j] = 0.0f;

        #pragma unroll
        for (int t = 0; t < 8; t++) {
            #pragma unroll
            for (int nb = 0; nb < 4; nb++) {
                int row = nb * 16 + (lane & 15);
                int col = t * 16 + ((lane >> 4) << 3);
                uint32_t off = (uint32_t)(row * 256 + (((col >> 3) ^ (row & 7)) << 4));
                uint32_t kh[4];
                ldsm_x4(kh, base + off);
                mma_f16(sf[2 * nb],     qh[t], kh[0], kh[2]);
                mma_f16(sf[2 * nb],     ql[t], kh[0], kh[2]);
                mma_f16(sf[2 * nb + 1], qh[t], kh[1], kh[3]);
                mma_f16(sf[2 * nb + 1], ql[t], kh[1], kh[3]);
            }
        }

        // ---- scale + causal mask
        const bool need_mask = (k0 + BK2 - 1) > (rbase);
        #pragma unroll
        for (int nf = 0; nf < 8; nf++)
            #pragma unroll
            for (int j = 0; j < 4; j++) {
                float s = sf[nf][j] * sc_scale;
                if (need_mask) {
                    int col = k0 + nf * 8 + (lane & 3) * 2 + (j & 1);
                    int row = rbase + (lane >> 2) + (j >> 1) * 8;
                    if (col > row) s = -INFINITY;
                }
                sf[nf][j] = s;
            }

        // ---- online softmax
        float mx0 = -INFINITY, mx1 = -INFINITY;
        #pragma unroll
        for (int nf = 0; nf < 8; nf++) {
            mx0 = fmaxf(mx0, fmaxf(sf[nf][0], sf[nf][1]));
            mx1 = fmaxf(mx1, fmaxf(sf[nf][2], sf[nf][3]));
        }
        mx0 = fmaxf(mx0, __shfl_xor_sync(0xffffffffu, mx0, 1));
        mx0 = fmaxf(mx0, __shfl_xor_sync(0xffffffffu, mx0, 2));
        mx1 = fmaxf(mx1, __shfl_xor_sync(0xffffffffu, mx1, 1));
        mx1 = fmaxf(mx1, __shfl_xor_sync(0xffffffffu, mx1, 2));

        float mn0 = fmaxf(m0, mx0), mn1 = fmaxf(m1, mx1);
        float cr0 = __expf(m0 - mn0), cr1 = __expf(m1 - mn1);

        float sum0 = 0.0f, sum1 = 0.0f;
        #pragma unroll
        for (int nf = 0; nf < 8; nf++) {
            float p0 = __expf(sf[nf][0] - mn0);
            float p1 = __expf(sf[nf][1] - mn0);
            float p2 = __expf(sf[nf][2] - mn1);
            float p3 = __expf(sf[nf][3] - mn1);
            sf[nf][0] = p0; sf[nf][1] = p1; sf[nf][2] = p2; sf[nf][3] = p3;
            sum0 += p0 + p1; sum1 += p2 + p3;
        }
        sum0 += __shfl_xor_sync(0xffffffffu, sum0, 1);
        sum0 += __shfl_xor_sync(0xffffffffu, sum0, 2);
        sum1 += __shfl_xor_sync(0xffffffffu, sum1, 1);
        sum1 += __shfl_xor_sync(0xffffffffu, sum1, 2);
        l0 = l0 * cr0 + sum0;  l1 = l1 * cr1 + sum1;
        m0 = mn0;  m1 = mn1;

        #pragma unroll
        for (int nf = 0; nf < 16; nf++) {
            O[nf][0] *= cr0; O[nf][1] *= cr0;
            O[nf][2] *= cr1; O[nf][3] *= cr1;
        }

        // ---- P -> A frags (fp16, single)
        uint32_t pa[4][4];
        #pragma unroll
        for (int kb = 0; kb < 4; kb++) {
            #pragma unroll
            for (int half = 0; half < 2; half++) {
                #pragma unroll
                for (int rr = 0; rr < 2; rr++) {
                    float f0 = sf[2 * kb + half][rr * 2];
                    float f1 = sf[2 * kb + half][rr * 2 + 1];
                    pa[kb][half * 2 + rr] = pack2h(__float2half(f0), __float2half(f1));
                }
            }
        }

        // ---- O += P V (fp16 single-pass)
        #pragma unroll
        for (int kb = 0; kb < 4; kb++) {
            #pragma unroll
            for (int nf2 = 0; nf2 < 8; nf2++) {
                int kk = kb * 16 + (lane & 15);
                int nn = nf2 * 16 + ((lane >> 4) << 3);
                uint32_t off = (uint32_t)(kk * 256 + (((nn >> 3) ^ (kk & 7)) << 4));
                uint32_t vh[4];
                ldsm_x4_t(vh, base + 16384 + off);
                mma_f16(O[2 * nf2],     pa[kb], vh[0], vh[1]);
                mma_f16(O[2 * nf2 + 1], pa[kb], vh[2], vh[3]);
            }
        }
        __syncthreads();
    }

    // ---- normalize + write z (single fp16) [b][s][h][d]
    float inv0 = 1.0f / l0, inv1 = 1.0f / l1;
    int r0 = rbase + (lane >> 2);
    size_t z0 = (((size_t)b * SEQ + r0) * NHEADS + h) * DHEAD;
    size_t z1 = (((size_t)b * SEQ + r0 + 8) * NHEADS + h) * DHEAD;
    #pragma unroll
    for (int nf = 0; nf < 16; nf++) {
        int col = nf * 8 + (lane & 3) * 2;
        *reinterpret_cast<uint32_t*>(&g_z[z0 + col]) =
            pack2h(__float2half(O[nf][0] * inv0), __float2half(O[nf][1] * inv0));
        *reinterpret_cast<uint32_t*>(&g_z[z1 + col]) =
            pack2h(__float2half(O[nf][2] * inv1), __float2half(O[nf][3] * inv1));
    }
}

// ---------------------------------------------------------------------------
extern "C" void kernel_launch(void* const* d_in, const int* in_sizes, int n_in,
                              void* d_out, int out_size)
{
    (void)in_sizes; (void)n_in; (void)out_size;
    const float* residual = (const float*)d_in[0];
    const float* WQ = (const float*)d_in[2];
    const float* WK = (const float*)d_in[3];
    const float* WV = (const float*)d_in[4];
    const float* WO = (const float*)d_in[5];
    const float* bQ = (const float*)d_in[6];
    const float* bK = (const float*)d_in[7];
    const float* bV = (const float*)d_in[8];
    const float* bO = (const float*)d_in[9];
    float* out = (float*)d_out;

    // tuple element 0: residual pass-through
    cudaMemcpyAsync(out, residual, (size_t)BATCH * SEQ * DMODEL * sizeof(float),
                    cudaMemcpyDeviceToDevice);

    // single fused conversion pre-pass
    dim3 gc(NTOK * DMODEL / 4 / 256, 5);
    convert_all<<<gc, 256>>>(residual, WQ, WK, WV, WO);

    cudaFuncSetAttribute(qkv_tc,  cudaFuncAttributeMaxDynamicSharedMemorySize, SM_GEMM1);
    cudaFuncSetAttribute(o_tc,    cudaFuncAttributeMaxDynamicSharedMemorySize, SM_GEMM1);
    cudaFuncSetAttribute(attn_tc, cudaFuncAttributeMaxDynamicSharedMemorySize, AT_SMEM);

    dim3 g1(NTOK / 128, NHEADS, 3);
    qkv_tc<<<g1, 256, SM_GEMM1>>>(bQ, bK, bV);

    dim3 g2(SEQ / BQ2, NHEADS, BATCH);
    attn_tc<<<g2, 256, AT_SMEM>>>();

    dim3 g3(NTOK / 128, DMODEL / 128);
    o_tc<<<g3, 256, SM_GEMM1>>>(bO, out + (size_t)BATCH * SEQ * DMODEL);
}

// round 13
// speedup vs baseline: 2.5900x; 1.0875x over previous
#include <cuda_runtime.h>
#include <cuda_bf16.h>
#include <cuda_fp16.h>
#include <math.h>
#include <stdint.h>

#define BATCH   2
#define SEQ     2048
#define DMODEL  2048
#define NHEADS  16
#define DHEAD   128
#define NTOK    (BATCH * SEQ)      // 4096

// ---------------- scratch (device globals; no allocation allowed) ----------
__device__ __align__(16) __half g_r[(size_t)NTOK * DMODEL];        // residual fp16
__device__ __align__(16) __half g_wq[(size_t)NHEADS * DMODEL * DHEAD];
__device__ __align__(16) __half g_wk[(size_t)NHEADS * DMODEL * DHEAD];
__device__ __align__(16) __half g_wv[(size_t)NHEADS * DMODEL * DHEAD];
__device__ __align__(16) __half g_wo[(size_t)DMODEL * DMODEL];
// attention operands [b][h][s][d]: all single fp16
__device__ __align__(16) __half g_q[(size_t)BATCH * NHEADS * SEQ * DHEAD];
__device__ __align__(16) __half g_k[(size_t)BATCH * NHEADS * SEQ * DHEAD];
__device__ __align__(16) __half g_v[(size_t)BATCH * NHEADS * SEQ * DHEAD];
// attention output: single fp16 [b][s][h][d]
__device__ __align__(16) __half g_z[(size_t)BATCH * SEQ * NHEADS * DHEAD];

// ========================= helpers =========================================
__device__ __forceinline__ void ldsm_x4(uint32_t r[4], uint32_t addr) {
    asm volatile("ldmatrix.sync.aligned.m8n8.x4.shared.b16 {%0,%1,%2,%3}, [%4];"
                 : "=r"(r[0]), "=r"(r[1]), "=r"(r[2]), "=r"(r[3]) : "r"(addr));
}
__device__ __forceinline__ void ldsm_x4_t(uint32_t r[4], uint32_t addr) {
    asm volatile("ldmatrix.sync.aligned.m8n8.x4.trans.shared.b16 {%0,%1,%2,%3}, [%4];"
                 : "=r"(r[0]), "=r"(r[1]), "=r"(r[2]), "=r"(r[3]) : "r"(addr));
}
__device__ __forceinline__ void mma_f16(float c[4], const uint32_t a[4],
                                        uint32_t b0, uint32_t b1) {
    asm volatile("mma.sync.aligned.m16n8k16.row.col.f32.f16.f16.f32 "
                 "{%0,%1,%2,%3}, {%4,%5,%6,%7}, {%8,%9}, {%0,%1,%2,%3};"
                 : "+f"(c[0]), "+f"(c[1]), "+f"(c[2]), "+f"(c[3])
                 : "r"(a[0]), "r"(a[1]), "r"(a[2]), "r"(a[3]), "r"(b0), "r"(b1));
}
__device__ __forceinline__ uint32_t smem_to_u32(const void* p) {
    uint32_t a;
    asm("{ .reg .u64 t; cvta.to.shared.u64 t, %1; cvt.u32.u64 %0, t; }"
        : "=r"(a) : "l"(p));
    return a;
}
__device__ __forceinline__ uint32_t pack2h(__half lo, __half hi) {
    return (uint32_t)__half_as_ushort(lo) | ((uint32_t)__half_as_ushort(hi) << 16);
}
__device__ __forceinline__ void cp_async16(uint32_t dst, const void* src) {
    asm volatile("cp.async.cg.shared.global [%0], [%1], 16;" :: "r"(dst), "l"(src));
}
__device__ __forceinline__ void cp_commit() {
    asm volatile("cp.async.commit_group;" ::: "memory");
}
__device__ __forceinline__ void cp_wait0() {
    asm volatile("cp.async.wait_group 0;" ::: "memory");
}
__device__ __forceinline__ void cp_wait1() {
    asm volatile("cp.async.wait_group 1;" ::: "memory");
}

// ===================== conversion pre-pass (single launch) =================
// which==0 also writes the residual pass-through output (replaces memcpy).
__global__ __launch_bounds__(256) void convert_all(
    const float* __restrict__ resid,
    const float* __restrict__ WQ, const float* __restrict__ WK,
    const float* __restrict__ WV, const float* __restrict__ WO,
    float* __restrict__ out_resid)
{
    const int which = blockIdx.y;
    int i = blockIdx.x * 256 + threadIdx.x;
    const float* src; __half* dst; int n4;
    switch (which) {
        case 0: src = resid; dst = g_r;  n4 = NTOK * DMODEL / 4; break;
        case 1: src = WQ;    dst = g_wq; n4 = NHEADS * DMODEL * DHEAD / 4; break;
        case 2: src = WK;    dst = g_wk; n4 = NHEADS * DMODEL * DHEAD / 4; break;
        case 3: src = WV;    dst = g_wv; n4 = NHEADS * DMODEL * DHEAD / 4; break;
        default:src = WO;    dst = g_wo; n4 = DMODEL * DMODEL / 4; break;
    }
    if (i >= n4) return;
    float4 v = reinterpret_cast<const float4*>(src)[i];
    reinterpret_cast<uint2*>(dst)[i] =
        make_uint2(pack2h(__float2half(v.x), __float2half(v.y)),
                   pack2h(__float2half(v.z), __float2half(v.w)));
    if (which == 0)
        reinterpret_cast<float4*>(out_resid)[i] = v;   // tuple element 0
}

// ===================== single-pass fp16 GEMM, KT=64 ========================
// 128x128 CTA tile, KT=64 k-step, 2-stage cp.async pipeline, 2 CTAs/SM.
// Stage (32KB): A [128 rows x 128B] @0, B [64 rows x 256B] @16384.
#define KT1    64
#define STG1   32768
#define SM_GEMM1 (2 * STG1)

__device__ __forceinline__ void gemm1_load_stage(
    uint32_t base, const __half* A, int lda,
    const __half* B, int ldb, int k0, int tid)
{
    #pragma unroll
    for (int it = 0; it < 4; it++) {             // A: 1024 chunks
        int idx = tid + it * 256;
        int m  = idx >> 3;
        int c8 = idx & 7;
        uint32_t d = base + (uint32_t)(m * 128 + ((c8 ^ (m & 7)) << 4));
        cp_async16(d, A + (size_t)m * lda + k0 + c8 * 8);
    }
    #pragma unroll
    for (int it = 0; it < 4; it++) {             // B: 1024 chunks
        int idx = tid + it * 256;
        int k  = idx >> 4;                       // 0..63
        int c8 = idx & 15;
        uint32_t d = base + 16384 + (uint32_t)(k * 256 + ((c8 ^ (k & 7)) << 4));
        cp_async16(d, B + (size_t)(k0 + k) * ldb + c8 * 8);
    }
}

__device__ __forceinline__ void gemm1_compute_stage(
    uint32_t base, int lane, int wm, int wn, float acc[4][4][4])
{
    #pragma unroll
    for (int k16 = 0; k16 < 4; k16++) {
        uint32_t bh[4][2];
        #pragma unroll
        for (int nf = 0; nf < 2; nf++) {
            int kk = k16 * 16 + (lane & 15);
            int nn = wn + nf * 16 + ((lane >> 4) << 3);
            uint32_t off = (uint32_t)(kk * 256 + (((nn >> 3) ^ (kk & 7)) << 4));
            uint32_t r[4];
            ldsm_x4_t(r, base + 16384 + off);
            bh[nf * 2][0] = r[0]; bh[nf * 2][1] = r[1];
            bh[nf * 2 + 1][0] = r[2]; bh[nf * 2 + 1][1] = r[3];
        }
        #pragma unroll
        for (int mi = 0; mi < 4; mi++) {
            int mm = wm + mi * 16 + (lane & 15);
            int c8 = k16 * 2 + (lane >> 4);      // 0..7
            uint32_t off = (uint32_t)(mm * 128 + ((c8 ^ (mm & 7)) << 4));
            uint32_t ah[4];
            ldsm_x4(ah, base + off);
            #pragma unroll
            for (int ni = 0; ni < 4; ni++)
                mma_f16(acc[mi][ni], ah, bh[ni][0], bh[ni][1]);
        }
    }
}

__device__ __forceinline__ void gemm1_mainloop(
    const __half* __restrict__ A, int lda,
    const __half* __restrict__ B, int ldb,
    char* smem, float acc[4][4][4])
{
    const int tid  = threadIdx.x;
    const int lane = tid & 31;
    const int wid  = tid >> 5;
    const int wm   = (wid >> 2) * 64;
    const int wn   = (wid & 3) * 32;
    const uint32_t sb = smem_to_u32(smem);
    const int NIT = DMODEL / KT1;                // 32

    gemm1_load_stage(sb, A, lda, B, ldb, 0, tid);
    cp_commit();

    for (int i = 0; i < NIT; i++) {
        if (i + 1 < NIT) {
            gemm1_load_stage(sb + ((i + 1) & 1) * STG1, A, lda, B, ldb,
                             (i + 1) * KT1, tid);
            cp_commit();
            cp_wait1();
        } else {
            cp_wait0();
        }
        __syncthreads();
        gemm1_compute_stage(sb + (i & 1) * STG1, lane, wm, wn, acc);
        __syncthreads();
    }
}

// ----------------------- QKV projection (single-pass fp16) -----------------
__global__ __launch_bounds__(256, 2) void qkv_tc(
    const float* __restrict__ bQ, const float* __restrict__ bK,
    const float* __restrict__ bV)
{
    extern __shared__ char smem[];
    const int i0 = blockIdx.x * 128;
    const int h  = blockIdx.y;
    const int which = blockIdx.z;

    const __half* W   = (which == 0) ? g_wq : (which == 1) ? g_wk : g_wv;
    const float* bias = (which == 0) ? bQ : (which == 1) ? bK : bV;
    __half* dst       = (which == 0) ? g_q : (which == 1) ? g_k : g_v;

    float acc[4][4][4];
    #pragma unroll
    for (int mi = 0; mi < 4; mi++)
        #pragma unroll
        for (int ni = 0; ni < 4; ni++)
            #pragma unroll
            for (int j = 0; j < 4; j++) acc[mi][ni][j] = 0.0f;

    gemm1_mainloop(g_r + (size_t)i0 * DMODEL, DMODEL,
                   W + (size_t)h * DMODEL * DHEAD, DHEAD, smem, acc);

    const int lane = threadIdx.x & 31;
    const int wid  = threadIdx.x >> 5;
    const int wm   = (wid >> 2) * 64;
    const int wn   = (wid & 3) * 32;
    #pragma unroll
    for (int mi = 0; mi < 4; mi++) {
        #pragma unroll
        for (int ni = 0; ni < 4; ni++) {
            int col = wn + ni * 8 + (lane & 3) * 2;
            float b0 = bias[h * DHEAD + col];
            float b1 = bias[h * DHEAD + col + 1];
            #pragma unroll
            for (int half = 0; half < 2; half++) {
                int i = i0 + wm + mi * 16 + (lane >> 2) + half * 8;
                int bb = i >> 11, s = i & 2047;
                size_t base = (((size_t)bb * NHEADS + h) * SEQ + s) * DHEAD + col;
                *reinterpret_cast<uint32_t*>(&dst[base]) =
                    pack2h(__float2half(acc[mi][ni][half * 2] + b0),
                           __float2half(acc[mi][ni][half * 2 + 1] + b1));
            }
        }
    }
}

// ----------------------- Output projection (single-pass fp16) --------------
__global__ __launch_bounds__(256, 2) void o_tc(
    const float* __restrict__ bO, float* __restrict__ out)
{
    extern __shared__ char smem[];
    const int i0 = blockIdx.x * 128;
    const int j0 = blockIdx.y * 128;

    float acc[4][4][4];
    #pragma unroll
    for (int mi = 0; mi < 4; mi++)
        #pragma unroll
        for (int ni = 0; ni < 4; ni++)
            #pragma unroll
            for (int j = 0; j < 4; j++) acc[mi][ni][j] = 0.0f;

    gemm1_mainloop(g_z + (size_t)i0 * DMODEL, DMODEL, g_wo + j0, DMODEL, smem, acc);

    const int lane = threadIdx.x & 31;
    const int wid  = threadIdx.x >> 5;
    const int wm   = (wid >> 2) * 64;
    const int wn   = (wid & 3) * 32;
    #pragma unroll
    for (int mi = 0; mi < 4; mi++) {
        #pragma unroll
        for (int ni = 0; ni < 4; ni++) {
            int col = j0 + wn + ni * 8 + (lane & 3) * 2;
            float b0 = bO[col], b1 = bO[col + 1];
            #pragma unroll
            for (int half = 0; half < 2; half++) {
                int i = i0 + wm + mi * 16 + (lane >> 2) + half * 8;
                float2 v = make_float2(acc[mi][ni][half * 2] + b0,
                                       acc[mi][ni][half * 2 + 1] + b1);
                *reinterpret_cast<float2*>(out + (size_t)i * DMODEL + col) = v;
            }
        }
    }
}

// ---------------------------------------------------------------------------
// Causal flash attention: single-pass fp16 both GEMMs.
// Stage (32KB): K @0 (16KB), V @16384. 2 stages = 64KB.
// ---------------------------------------------------------------------------
#define BQ2 128
#define BK2 64
#define ATSTG 32768
#define AT_SMEM (2 * ATSTG)

__device__ __forceinline__ void attn_load_kv(
    uint32_t base, const __half* Kg, const __half* Vg, int k0, int tid)
{
    #pragma unroll
    for (int it = 0; it < 4; it++) {
        int idx = tid + it * 256;                // 0..1023
        int r  = idx >> 4;
        int c8 = idx & 15;
        uint32_t d = (uint32_t)(r * 256 + ((c8 ^ (r & 7)) << 4));
        size_t so = (size_t)(k0 + r) * DHEAD + c8 * 8;
        cp_async16(base + d,         Kg + so);
        cp_async16(base + 16384 + d, Vg + so);
    }
}

__global__ __launch_bounds__(256, 1) void attn_tc()
{
    extern __shared__ char smem[];
    const uint32_t sb = smem_to_u32(smem);
    const int tid  = threadIdx.x;
    const int lane = tid & 31;
    const int w    = tid >> 5;
    const int q0   = blockIdx.x * BQ2;
    const int h    = blockIdx.y;
    const int b    = blockIdx.z;

    const size_t head_off = ((size_t)b * NHEADS + h) * SEQ * DHEAD;
    const __half* Qg = g_q + head_off + (size_t)q0 * DHEAD;
    const __half* Kg = g_k + head_off;
    const __half* Vg = g_v + head_off;

    const int NIT = (q0 + BQ2) / BK2;

    // ---- Q prologue (single fp16)
    #pragma unroll
    for (int it = 0; it < 8; it++) {
        int idx = tid + it * 256;
        int m  = idx >> 4;
        int c8 = idx & 15;
        uint32_t d = (uint32_t)(m * 256 + ((c8 ^ (m & 7)) << 4));
        cp_async16(sb + d, Qg + (size_t)m * DHEAD + c8 * 8);
    }
    cp_commit();
    cp_wait0();
    __syncthreads();

    uint32_t qh[8][4];
    #pragma unroll
    for (int t = 0; t < 8; t++) {
        int row = w * 16 + (lane & 15);
        int col = t * 16 + ((lane >> 4) << 3);
        uint32_t off = (uint32_t)(row * 256 + (((col >> 3) ^ (row & 7)) << 4));
        ldsm_x4(qh[t], sb + off);
    }
    __syncthreads();

    attn_load_kv(sb, Kg, Vg, 0, tid);
    cp_commit();

    float O[16][4];
    #pragma unroll
    for (int nf = 0; nf < 16; nf++)
        #pragma unroll
        for (int j = 0; j < 4; j++) O[nf][j] = 0.0f;
    float m0 = -INFINITY, m1 = -INFINITY, l0 = 0.0f, l1 = 0.0f;

    const float sc_scale = 0.08838834764831843f;
    const int rbase = q0 + w * 16;

    for (int i = 0; i < NIT; i++) {
        const int k0 = i * BK2;
        if (i + 1 < NIT) {
            attn_load_kv(sb + ((i + 1) & 1) * ATSTG, Kg, Vg, (i + 1) * BK2, tid);
            cp_commit();
            cp_wait1();
        } else {
            cp_wait0();
        }
        __syncthreads();
        const uint32_t base = sb + (i & 1) * ATSTG;

        // ---- S = Q K^T (fp16 single-pass)
        float sf[8][4];
        #pragma unroll
        for (int nf = 0; nf < 8; nf++)
            #pragma unroll
            for (int j = 0; j < 4; j++) sf[nf][j] = 0.0f;

        #pragma unroll
        for (int t = 0; t < 8; t++) {
            #pragma unroll
            for (int nb = 0; nb < 4; nb++) {
                int row = nb * 16 + (lane & 15);
                int col = t * 16 + ((lane >> 4) << 3);
                uint32_t off = (uint32_t)(row * 256 + (((col >> 3) ^ (row & 7)) << 4));
                uint32_t kh[4];
                ldsm_x4(kh, base + off);
                mma_f16(sf[2 * nb],     qh[t], kh[0], kh[2]);
                mma_f16(sf[2 * nb + 1], qh[t], kh[1], kh[3]);
            }
        }

        // ---- scale + causal mask
        const bool need_mask = (k0 + BK2 - 1) > (rbase);
        #pragma unroll
        for (int nf = 0; nf < 8; nf++)
            #pragma unroll
            for (int j = 0; j < 4; j++) {
                float s = sf[nf][j] * sc_scale;
                if (need_mask) {
                    int col = k0 + nf * 8 + (lane & 3) * 2 + (j & 1);
                    int row = rbase + (lane >> 2) + (j >> 1) * 8;
                    if (col > row) s = -INFINITY;
                }
                sf[nf][j] = s;
            }

        // ---- online softmax
        float mx0 = -INFINITY, mx1 = -INFINITY;
        #pragma unroll
        for (int nf = 0; nf < 8; nf++) {
            mx0 = fmaxf(mx0, fmaxf(sf[nf][0], sf[nf][1]));
            mx1 = fmaxf(mx1, fmaxf(sf[nf][2], sf[nf][3]));
        }
        mx0 = fmaxf(mx0, __shfl_xor_sync(0xffffffffu, mx0, 1));
        mx0 = fmaxf(mx0, __shfl_xor_sync(0xffffffffu, mx0, 2));
        mx1 = fmaxf(mx1, __shfl_xor_sync(0xffffffffu, mx1, 1));
        mx1 = fmaxf(mx1, __shfl_xor_sync(0xffffffffu, mx1, 2));

        float mn0 = fmaxf(m0, mx0), mn1 = fmaxf(m1, mx1);
        float cr0 = __expf(m0 - mn0), cr1 = __expf(m1 - mn1);

        float sum0 = 0.0f, sum1 = 0.0f;
        #pragma unroll
        for (int nf = 0; nf < 8; nf++) {
            float p0 = __expf(sf[nf][0] - mn0);
            float p1 = __expf(sf[nf][1] - mn0);
            float p2 = __expf(sf[nf][2] - mn1);
            float p3 = __expf(sf[nf][3] - mn1);
            sf[nf][0] = p0; sf[nf][1] = p1; sf[nf][2] = p2; sf[nf][3] = p3;
            sum0 += p0 + p1; sum1 += p2 + p3;
        }
        sum0 += __shfl_xor_sync(0xffffffffu, sum0, 1);
        sum0 += __shfl_xor_sync(0xffffffffu, sum0, 2);
        sum1 += __shfl_xor_sync(0xffffffffu, sum1, 1);
        sum1 += __shfl_xor_sync(0xffffffffu, sum1, 2);
        l0 = l0 * cr0 + sum0;  l1 = l1 * cr1 + sum1;
        m0 = mn0;  m1 = mn1;

        #pragma unroll
        for (int nf = 0; nf < 16; nf++) {
            O[nf][0] *= cr0; O[nf][1] *= cr0;
            O[nf][2] *= cr1; O[nf][3] *= cr1;
        }

        // ---- P -> A frags (fp16, single)
        uint32_t pa[4][4];
        #pragma unroll
        for (int kb = 0; kb < 4; kb++) {
            #pragma unroll
            for (int half = 0; half < 2; half++) {
                #pragma unroll
                for (int rr = 0; rr < 2; rr++) {
                    float f0 = sf[2 * kb + half][rr * 2];
                    float f1 = sf[2 * kb + half][rr * 2 + 1];
                    pa[kb][half * 2 + rr] = pack2h(__float2half(f0), __float2half(f1));
                }
            }
        }

        // ---- O += P V (fp16 single-pass)
        #pragma unroll
        for (int kb = 0; kb < 4; kb++) {
            #pragma unroll
            for (int nf2 = 0; nf2 < 8; nf2++) {
                int kk = kb * 16 + (lane & 15);
                int nn = nf2 * 16 + ((lane >> 4) << 3);
                uint32_t off = (uint32_t)(kk * 256 + (((nn >> 3) ^ (kk & 7)) << 4));
                uint32_t vh[4];
                ldsm_x4_t(vh, base + 16384 + off);
                mma_f16(O[2 * nf2],     pa[kb], vh[0], vh[1]);
                mma_f16(O[2 * nf2 + 1], pa[kb], vh[2], vh[3]);
            }
        }
        __syncthreads();
    }

    // ---- normalize + write z (single fp16) [b][s][h][d]
    float inv0 = 1.0f / l0, inv1 = 1.0f / l1;
    int r0 = rbase + (lane >> 2);
    size_t z0 = (((size_t)b * SEQ + r0) * NHEADS + h) * DHEAD;
    size_t z1 = (((size_t)b * SEQ + r0 + 8) * NHEADS + h) * DHEAD;
    #pragma unroll
    for (int nf = 0; nf < 16; nf++) {
        int col = nf * 8 + (lane & 3) * 2;
        *reinterpret_cast<uint32_t*>(&g_z[z0 + col]) =
            pack2h(__float2half(O[nf][0] * inv0), __float2half(O[nf][1] * inv0));
        *reinterpret_cast<uint32_t*>(&g_z[z1 + col]) =
            pack2h(__float2half(O[nf][2] * inv1), __float2half(O[nf][3] * inv1));
    }
}

// ---------------------------------------------------------------------------
extern "C" void kernel_launch(void* const* d_in, const int* in_sizes, int n_in,
                              void* d_out, int out_size)
{
    (void)in_sizes; (void)n_in; (void)out_size;
    const float* residual = (const float*)d_in[0];
    const float* WQ = (const float*)d_in[2];
    const float* WK = (const float*)d_in[3];
    const float* WV = (const float*)d_in[4];
    const float* WO = (const float*)d_in[5];
    const float* bQ = (const float*)d_in[6];
    const float* bK = (const float*)d_in[7];
    const float* bV = (const float*)d_in[8];
    const float* bO = (const float*)d_in[9];
    float* out = (float*)d_out;

    // fused conversion pre-pass (also writes residual pass-through to out)
    dim3 gc(NTOK * DMODEL / 4 / 256, 5);
    convert_all<<<gc, 256>>>(residual, WQ, WK, WV, WO, out);

    cudaFuncSetAttribute(qkv_tc,  cudaFuncAttributeMaxDynamicSharedMemorySize, SM_GEMM1);
    cudaFuncSetAttribute(o_tc,    cudaFuncAttributeMaxDynamicSharedMemorySize, SM_GEMM1);
    cudaFuncSetAttribute(attn_tc, cudaFuncAttributeMaxDynamicSharedMemorySize, AT_SMEM);

    dim3 g1(NTOK / 128, NHEADS, 3);
    qkv_tc<<<g1, 256, SM_GEMM1>>>(bQ, bK, bV);

    dim3 g2(SEQ / BQ2, NHEADS, BATCH);
    attn_tc<<<g2, 256, AT_SMEM>>>();

    dim3 g3(NTOK / 128, DMODEL / 128);
    o_tc<<<g3, 256, SM_GEMM1>>>(bO, out + (size_t)BATCH * SEQ * DMODEL);
}

// round 14
// speedup vs baseline: 2.6612x; 1.0275x over previous
#include <cuda_runtime.h>
#include <cuda_bf16.h>
#include <cuda_fp16.h>
#include <math.h>
#include <stdint.h>

#define BATCH   2
#define SEQ     2048
#define DMODEL  2048
#define NHEADS  16
#define DHEAD   128
#define NTOK    (BATCH * SEQ)      // 4096

// ---------------- scratch (device globals; no allocation allowed) ----------
__device__ __align__(16) __half g_r[(size_t)NTOK * DMODEL];        // residual fp16
__device__ __align__(16) __half g_wq[(size_t)NHEADS * DMODEL * DHEAD];
__device__ __align__(16) __half g_wk[(size_t)NHEADS * DMODEL * DHEAD];
__device__ __align__(16) __half g_wv[(size_t)NHEADS * DMODEL * DHEAD];
__device__ __align__(16) __half g_wo[(size_t)DMODEL * DMODEL];
// attention operands [b][h][s][d]: all single fp16
__device__ __align__(16) __half g_q[(size_t)BATCH * NHEADS * SEQ * DHEAD];
__device__ __align__(16) __half g_k[(size_t)BATCH * NHEADS * SEQ * DHEAD];
__device__ __align__(16) __half g_v[(size_t)BATCH * NHEADS * SEQ * DHEAD];
// attention output: single fp16 [b][s][h][d]
__device__ __align__(16) __half g_z[(size_t)BATCH * SEQ * NHEADS * DHEAD];

// ========================= helpers =========================================
__device__ __forceinline__ void ldsm_x4(uint32_t r[4], uint32_t addr) {
    asm volatile("ldmatrix.sync.aligned.m8n8.x4.shared.b16 {%0,%1,%2,%3}, [%4];"
                 : "=r"(r[0]), "=r"(r[1]), "=r"(r[2]), "=r"(r[3]) : "r"(addr));
}
__device__ __forceinline__ void ldsm_x4_t(uint32_t r[4], uint32_t addr) {
    asm volatile("ldmatrix.sync.aligned.m8n8.x4.trans.shared.b16 {%0,%1,%2,%3}, [%4];"
                 : "=r"(r[0]), "=r"(r[1]), "=r"(r[2]), "=r"(r[3]) : "r"(addr));
}
__device__ __forceinline__ void mma_f16(float c[4], const uint32_t a[4],
                                        uint32_t b0, uint32_t b1) {
    asm volatile("mma.sync.aligned.m16n8k16.row.col.f32.f16.f16.f32 "
                 "{%0,%1,%2,%3}, {%4,%5,%6,%7}, {%8,%9}, {%0,%1,%2,%3};"
                 : "+f"(c[0]), "+f"(c[1]), "+f"(c[2]), "+f"(c[3])
                 : "r"(a[0]), "r"(a[1]), "r"(a[2]), "r"(a[3]), "r"(b0), "r"(b1));
}
__device__ __forceinline__ uint32_t smem_to_u32(const void* p) {
    uint32_t a;
    asm("{ .reg .u64 t; cvta.to.shared.u64 t, %1; cvt.u32.u64 %0, t; }"
        : "=r"(a) : "l"(p));
    return a;
}
__device__ __forceinline__ uint32_t pack2h(__half lo, __half hi) {
    return (uint32_t)__half_as_ushort(lo) | ((uint32_t)__half_as_ushort(hi) << 16);
}
__device__ __forceinline__ void cp_async16(uint32_t dst, const void* src) {
    asm volatile("cp.async.cg.shared.global [%0], [%1], 16;" :: "r"(dst), "l"(src));
}
__device__ __forceinline__ void cp_commit() {
    asm volatile("cp.async.commit_group;" ::: "memory");
}
__device__ __forceinline__ void cp_wait0() {
    asm volatile("cp.async.wait_group 0;" ::: "memory");
}
__device__ __forceinline__ void cp_wait1() {
    asm volatile("cp.async.wait_group 1;" ::: "memory");
}

// ===================== conversion pre-pass (single launch) =================
__global__ __launch_bounds__(256) void convert_all(
    const float* __restrict__ resid,
    const float* __restrict__ WQ, const float* __restrict__ WK,
    const float* __restrict__ WV, const float* __restrict__ WO,
    float* __restrict__ out_resid)
{
    const int which = blockIdx.y;
    int i = blockIdx.x * 256 + threadIdx.x;
    const float* src; __half* dst; int n4;
    switch (which) {
        case 0: src = resid; dst = g_r;  n4 = NTOK * DMODEL / 4; break;
        case 1: src = WQ;    dst = g_wq; n4 = NHEADS * DMODEL * DHEAD / 4; break;
        case 2: src = WK;    dst = g_wk; n4 = NHEADS * DMODEL * DHEAD / 4; break;
        case 3: src = WV;    dst = g_wv; n4 = NHEADS * DMODEL * DHEAD / 4; break;
        default:src = WO;    dst = g_wo; n4 = DMODEL * DMODEL / 4; break;
    }
    if (i >= n4) return;
    float4 v = reinterpret_cast<const float4*>(src)[i];
    reinterpret_cast<uint2*>(dst)[i] =
        make_uint2(pack2h(__float2half(v.x), __float2half(v.y)),
                   pack2h(__float2half(v.z), __float2half(v.w)));
    if (which == 0)
        reinterpret_cast<float4*>(out_resid)[i] = v;   // tuple element 0
}

// ===================== single-pass fp16 GEMM, KT=64 ========================
#define KT1    64
#define STG1   32768
#define SM_GEMM1 (2 * STG1)

__device__ __forceinline__ void gemm1_load_stage(
    uint32_t base, const __half* A, int lda,
    const __half* B, int ldb, int k0, int tid)
{
    #pragma unroll
    for (int it = 0; it < 4; it++) {             // A: 1024 chunks
        int idx = tid + it * 256;
        int m  = idx >> 3;
        int c8 = idx & 7;
        uint32_t d = base + (uint32_t)(m * 128 + ((c8 ^ (m & 7)) << 4));
        cp_async16(d, A + (size_t)m * lda + k0 + c8 * 8);
    }
    #pragma unroll
    for (int it = 0; it < 4; it++) {             // B: 1024 chunks
        int idx = tid + it * 256;
        int k  = idx >> 4;                       // 0..63
        int c8 = idx & 15;
        uint32_t d = base + 16384 + (uint32_t)(k * 256 + ((c8 ^ (k & 7)) << 4));
        cp_async16(d, B + (size_t)(k0 + k) * ldb + c8 * 8);
    }
}

__device__ __forceinline__ void gemm1_compute_stage(
    uint32_t base, int lane, int wm, int wn, float acc[4][4][4])
{
    #pragma unroll
    for (int k16 = 0; k16 < 4; k16++) {
        uint32_t bh[4][2];
        #pragma unroll
        for (int nf = 0; nf < 2; nf++) {
            int kk = k16 * 16 + (lane & 15);
            int nn = wn + nf * 16 + ((lane >> 4) << 3);
            uint32_t off = (uint32_t)(kk * 256 + (((nn >> 3) ^ (kk & 7)) << 4));
            uint32_t r[4];
            ldsm_x4_t(r, base + 16384 + off);
            bh[nf * 2][0] = r[0]; bh[nf * 2][1] = r[1];
            bh[nf * 2 + 1][0] = r[2]; bh[nf * 2 + 1][1] = r[3];
        }
        #pragma unroll
        for (int mi = 0; mi < 4; mi++) {
            int mm = wm + mi * 16 + (lane & 15);
            int c8 = k16 * 2 + (lane >> 4);      // 0..7
            uint32_t off = (uint32_t)(mm * 128 + ((c8 ^ (mm & 7)) << 4));
            uint32_t ah[4];
            ldsm_x4(ah, base + off);
            #pragma unroll
            for (int ni = 0; ni < 4; ni++)
                mma_f16(acc[mi][ni], ah, bh[ni][0], bh[ni][1]);
        }
    }
}

__device__ __forceinline__ void gemm1_mainloop(
    const __half* __restrict__ A, int lda,
    const __half* __restrict__ B, int ldb,
    char* smem, float acc[4][4][4])
{
    const int tid  = threadIdx.x;
    const int lane = tid & 31;
    const int wid  = tid >> 5;
    const int wm   = (wid >> 2) * 64;
    const int wn   = (wid & 3) * 32;
    const uint32_t sb = smem_to_u32(smem);
    const int NIT = DMODEL / KT1;                // 32

    gemm1_load_stage(sb, A, lda, B, ldb, 0, tid);
    cp_commit();

    for (int i = 0; i < NIT; i++) {
        if (i + 1 < NIT) {
            gemm1_load_stage(sb + ((i + 1) & 1) * STG1, A, lda, B, ldb,
                             (i + 1) * KT1, tid);
            cp_commit();
            cp_wait1();
        } else {
            cp_wait0();
        }
        __syncthreads();
        gemm1_compute_stage(sb + (i & 1) * STG1, lane, wm, wn, acc);
        __syncthreads();
    }
}

// ----------------------- QKV projection (single-pass fp16) -----------------
__global__ __launch_bounds__(256, 2) void qkv_tc(
    const float* __restrict__ bQ, const float* __restrict__ bK,
    const float* __restrict__ bV)
{
    extern __shared__ char smem[];
    const int i0 = blockIdx.x * 128;
    const int h  = blockIdx.y;
    const int which = blockIdx.z;

    const __half* W   = (which == 0) ? g_wq : (which == 1) ? g_wk : g_wv;
    const float* bias = (which == 0) ? bQ : (which == 1) ? bK : bV;
    __half* dst       = (which == 0) ? g_q : (which == 1) ? g_k : g_v;

    float acc[4][4][4];
    #pragma unroll
    for (int mi = 0; mi < 4; mi++)
        #pragma unroll
        for (int ni = 0; ni < 4; ni++)
            #pragma unroll
            for (int j = 0; j < 4; j++) acc[mi][ni][j] = 0.0f;

    gemm1_mainloop(g_r + (size_t)i0 * DMODEL, DMODEL,
                   W + (size_t)h * DMODEL * DHEAD, DHEAD, smem, acc);

    const int lane = threadIdx.x & 31;
    const int wid  = threadIdx.x >> 5;
    const int wm   = (wid >> 2) * 64;
    const int wn   = (wid & 3) * 32;
    #pragma unroll
    for (int mi = 0; mi < 4; mi++) {
        #pragma unroll
        for (int ni = 0; ni < 4; ni++) {
            int col = wn + ni * 8 + (lane & 3) * 2;
            float b0 = bias[h * DHEAD + col];
            float b1 = bias[h * DHEAD + col + 1];
            #pragma unroll
            for (int half = 0; half < 2; half++) {
                int i = i0 + wm + mi * 16 + (lane >> 2) + half * 8;
                int bb = i >> 11, s = i & 2047;
                size_t base = (((size_t)bb * NHEADS + h) * SEQ + s) * DHEAD + col;
                *reinterpret_cast<uint32_t*>(&dst[base]) =
                    pack2h(__float2half(acc[mi][ni][half * 2] + b0),
                           __float2half(acc[mi][ni][half * 2 + 1] + b1));
            }
        }
    }
}

// ----------------------- Output projection (single-pass fp16) --------------
__global__ __launch_bounds__(256, 2) void o_tc(
    const float* __restrict__ bO, float* __restrict__ out)
{
    extern __shared__ char smem[];
    const int i0 = blockIdx.x * 128;
    const int j0 = blockIdx.y * 128;

    float acc[4][4][4];
    #pragma unroll
    for (int mi = 0; mi < 4; mi++)
        #pragma unroll
        for (int ni = 0; ni < 4; ni++)
            #pragma unroll
            for (int j = 0; j < 4; j++) acc[mi][ni][j] = 0.0f;

    gemm1_mainloop(g_z + (size_t)i0 * DMODEL, DMODEL, g_wo + j0, DMODEL, smem, acc);

    const int lane = threadIdx.x & 31;
    const int wid  = threadIdx.x >> 5;
    const int wm   = (wid >> 2) * 64;
    const int wn   = (wid & 3) * 32;
    #pragma unroll
    for (int mi = 0; mi < 4; mi++) {
        #pragma unroll
        for (int ni = 0; ni < 4; ni++) {
            int col = j0 + wn + ni * 8 + (lane & 3) * 2;
            float b0 = bO[col], b1 = bO[col + 1];
            #pragma unroll
            for (int half = 0; half < 2; half++) {
                int i = i0 + wm + mi * 16 + (lane >> 2) + half * 8;
                float2 v = make_float2(acc[mi][ni][half * 2] + b0,
                                       acc[mi][ni][half * 2 + 1] + b1);
                *reinterpret_cast<float2*>(out + (size_t)i * DMODEL + col) = v;
            }
        }
    }
}

// ---------------------------------------------------------------------------
// Causal flash attention: single-pass fp16, BK2=128 kv-tiles, heavy-first.
// Stage (64KB): K @0 (32KB), V @32768. 2 stages = 128KB.
// ---------------------------------------------------------------------------
#define BQ2 128
#define BK2 128
#define ATSTG 65536
#define AT_SMEM (2 * ATSTG)

__device__ __forceinline__ void attn_load_kv(
    uint32_t base, const __half* Kg, const __half* Vg, int k0, int tid)
{
    #pragma unroll
    for (int it = 0; it < 8; it++) {
        int idx = tid + it * 256;                // 0..2047
        int r  = idx >> 4;                       // 0..127
        int c8 = idx & 15;
        uint32_t d = (uint32_t)(r * 256 + ((c8 ^ (r & 7)) << 4));
        size_t so = (size_t)(k0 + r) * DHEAD + c8 * 8;
        cp_async16(base + d,         Kg + so);
        cp_async16(base + 32768 + d, Vg + so);
    }
}

__global__ __launch_bounds__(256, 1) void attn_tc()
{
    extern __shared__ char smem[];
    const uint32_t sb = smem_to_u32(smem);
    const int tid  = threadIdx.x;
    const int lane = tid & 31;
    const int w    = tid >> 5;
    const int qi   = gridDim.x - 1 - blockIdx.x;   // heavy tiles launch first
    const int q0   = qi * BQ2;
    const int h    = blockIdx.y;
    const int b    = blockIdx.z;

    const size_t head_off = ((size_t)b * NHEADS + h) * SEQ * DHEAD;
    const __half* Qg = g_q + head_off + (size_t)q0 * DHEAD;
    const __half* Kg = g_k + head_off;
    const __half* Vg = g_v + head_off;

    const int NIT = (q0 + BQ2) / BK2;              // qi + 1

    // ---- Q prologue (single fp16) into stage-0 K area
    #pragma unroll
    for (int it = 0; it < 8; it++) {
        int idx = tid + it * 256;
        int m  = idx >> 4;
        int c8 = idx & 15;
        uint32_t d = (uint32_t)(m * 256 + ((c8 ^ (m & 7)) << 4));
        cp_async16(sb + d, Qg + (size_t)m * DHEAD + c8 * 8);
    }
    cp_commit();
    cp_wait0();
    __syncthreads();

    uint32_t qh[8][4];
    #pragma unroll
    for (int t = 0; t < 8; t++) {
        int row = w * 16 + (lane & 15);
        int col = t * 16 + ((lane >> 4) << 3);
        uint32_t off = (uint32_t)(row * 256 + (((col >> 3) ^ (row & 7)) << 4));
        ldsm_x4(qh[t], sb + off);
    }
    __syncthreads();

    attn_load_kv(sb, Kg, Vg, 0, tid);
    cp_commit();

    float O[16][4];
    #pragma unroll
    for (int nf = 0; nf < 16; nf++)
        #pragma unroll
        for (int j = 0; j < 4; j++) O[nf][j] = 0.0f;
    float m0 = -INFINITY, m1 = -INFINITY, l0 = 0.0f, l1 = 0.0f;

    const float sc_scale = 0.08838834764831843f;
    const int rbase = q0 + w * 16;

    for (int i = 0; i < NIT; i++) {
        const int k0 = i * BK2;
        if (i + 1 < NIT) {
            attn_load_kv(sb + ((i + 1) & 1) * ATSTG, Kg, Vg, (i + 1) * BK2, tid);
            cp_commit();
            cp_wait1();
        } else {
            cp_wait0();
        }
        __syncthreads();
        const uint32_t base = sb + (i & 1) * ATSTG;

        // ---- S = Q K^T (fp16 single-pass), 128 cols -> 16 n-frags
        float sf[16][4];
        #pragma unroll
        for (int nf = 0; nf < 16; nf++)
            #pragma unroll
            for (int j = 0; j < 4; j++) sf[nf][j] = 0.0f;

        #pragma unroll
        for (int t = 0; t < 8; t++) {
            #pragma unroll
            for (int nb = 0; nb < 8; nb++) {
                int row = nb * 16 + (lane & 15);
                int col = t * 16 + ((lane >> 4) << 3);
                uint32_t off = (uint32_t)(row * 256 + (((col >> 3) ^ (row & 7)) << 4));
                uint32_t kh[4];
                ldsm_x4(kh, base + off);
                mma_f16(sf[2 * nb],     qh[t], kh[0], kh[2]);
                mma_f16(sf[2 * nb + 1], qh[t], kh[1], kh[3]);
            }
        }

        // ---- scale + causal mask (diagonal tile only)
        const bool need_mask = (k0 + BK2 - 1) > (rbase);
        #pragma unroll
        for (int nf = 0; nf < 16; nf++)
            #pragma unroll
            for (int j = 0; j < 4; j++) {
                float s = sf[nf][j] * sc_scale;
                if (need_mask) {
                    int col = k0 + nf * 8 + (lane & 3) * 2 + (j & 1);
                    int row = rbase + (lane >> 2) + (j >> 1) * 8;
                    if (col > row) s = -INFINITY;
                }
                sf[nf][j] = s;
            }

        // ---- online softmax
        float mx0 = -INFINITY, mx1 = -INFINITY;
        #pragma unroll
        for (int nf = 0; nf < 16; nf++) {
            mx0 = fmaxf(mx0, fmaxf(sf[nf][0], sf[nf][1]));
            mx1 = fmaxf(mx1, fmaxf(sf[nf][2], sf[nf][3]));
        }
        mx0 = fmaxf(mx0, __shfl_xor_sync(0xffffffffu, mx0, 1));
        mx0 = fmaxf(mx0, __shfl_xor_sync(0xffffffffu, mx0, 2));
        mx1 = fmaxf(mx1, __shfl_xor_sync(0xffffffffu, mx1, 1));
        mx1 = fmaxf(mx1, __shfl_xor_sync(0xffffffffu, mx1, 2));

        float mn0 = fmaxf(m0, mx0), mn1 = fmaxf(m1, mx1);
        float cr0 = __expf(m0 - mn0), cr1 = __expf(m1 - mn1);

        float sum0 = 0.0f, sum1 = 0.0f;
        #pragma unroll
        for (int nf = 0; nf < 16; nf++) {
            float p0 = __expf(sf[nf][0] - mn0);
            float p1 = __expf(sf[nf][1] - mn0);
            float p2 = __expf(sf[nf][2] - mn1);
            float p3 = __expf(sf[nf][3] - mn1);
            sf[nf][0] = p0; sf[nf][1] = p1; sf[nf][2] = p2; sf[nf][3] = p3;
            sum0 += p0 + p1; sum1 += p2 + p3;
        }
        sum0 += __shfl_xor_sync(0xffffffffu, sum0, 1);
        sum0 += __shfl_xor_sync(0xffffffffu, sum0, 2);
        sum1 += __shfl_xor_sync(0xffffffffu, sum1, 1);
        sum1 += __shfl_xor_sync(0xffffffffu, sum1, 2);
        l0 = l0 * cr0 + sum0;  l1 = l1 * cr1 + sum1;
        m0 = mn0;  m1 = mn1;

        #pragma unroll
        for (int nf = 0; nf < 16; nf++) {
            O[nf][0] *= cr0; O[nf][1] *= cr0;
            O[nf][2] *= cr1; O[nf][3] *= cr1;
        }

        // ---- P -> A frags (fp16, single); 8 k-blocks of 16
        uint32_t pa[8][4];
        #pragma unroll
        for (int kb = 0; kb < 8; kb++) {
            #pragma unroll
            for (int half = 0; half < 2; half++) {
                #pragma unroll
                for (int rr = 0; rr < 2; rr++) {
                    float f0 = sf[2 * kb + half][rr * 2];
                    float f1 = sf[2 * kb + half][rr * 2 + 1];
                    pa[kb][half * 2 + rr] = pack2h(__float2half(f0), __float2half(f1));
                }
            }
        }

        // ---- O += P V (fp16 single-pass)
        #pragma unroll
        for (int kb = 0; kb < 8; kb++) {
            #pragma unroll
            for (int nf2 = 0; nf2 < 8; nf2++) {
                int kk = kb * 16 + (lane & 15);
                int nn = nf2 * 16 + ((lane >> 4) << 3);
                uint32_t off = (uint32_t)(kk * 256 + (((nn >> 3) ^ (kk & 7)) << 4));
                uint32_t vh[4];
                ldsm_x4_t(vh, base + 32768 + off);
                mma_f16(O[2 * nf2],     pa[kb], vh[0], vh[1]);
                mma_f16(O[2 * nf2 + 1], pa[kb], vh[2], vh[3]);
            }
        }
        __syncthreads();
    }

    // ---- normalize + write z (single fp16) [b][s][h][d]
    float inv0 = 1.0f / l0, inv1 = 1.0f / l1;
    int r0 = rbase + (lane >> 2);
    size_t z0 = (((size_t)b * SEQ + r0) * NHEADS + h) * DHEAD;
    size_t z1 = (((size_t)b * SEQ + r0 + 8) * NHEADS + h) * DHEAD;
    #pragma unroll
    for (int nf = 0; nf < 16; nf++) {
        int col = nf * 8 + (lane & 3) * 2;
        *reinterpret_cast<uint32_t*>(&g_z[z0 + col]) =
            pack2h(__float2half(O[nf][0] * inv0), __float2half(O[nf][1] * inv0));
        *reinterpret_cast<uint32_t*>(&g_z[z1 + col]) =
            pack2h(__float2half(O[nf][2] * inv1), __float2half(O[nf][3] * inv1));
    }
}

// ---------------------------------------------------------------------------
extern "C" void kernel_launch(void* const* d_in, const int* in_sizes, int n_in,
                              void* d_out, int out_size)
{
    (void)in_sizes; (void)n_in; (void)out_size;
    const float* residual = (const float*)d_in[0];
    const float* WQ = (const float*)d_in[2];
    const float* WK = (const float*)d_in[3];
    const float* WV = (const float*)d_in[4];
    const float* WO = (const float*)d_in[5];
    const float* bQ = (const float*)d_in[6];
    const float* bK = (const float*)d_in[7];
    const float* bV = (const float*)d_in[8];
    const float* bO = (const float*)d_in[9];
    float* out = (float*)d_out;

    // fused conversion pre-pass (also writes residual pass-through to out)
    dim3 gc(NTOK * DMODEL / 4 / 256, 5);
    convert_all<<<gc, 256>>>(residual, WQ, WK, WV, WO, out);

    cudaFuncSetAttribute(qkv_tc,  cudaFuncAttributeMaxDynamicSharedMemorySize, SM_GEMM1);
    cudaFuncSetAttribute(o_tc,    cudaFuncAttributeMaxDynamicSharedMemorySize, SM_GEMM1);
    cudaFuncSetAttribute(attn_tc, cudaFuncAttributeMaxDynamicSharedMemorySize, AT_SMEM);

    dim3 g1(NTOK / 128, NHEADS, 3);
    qkv_tc<<<g1, 256, SM_GEMM1>>>(bQ, bK, bV);

    dim3 g2(SEQ / BQ2, NHEADS, BATCH);
    attn_tc<<<g2, 256, AT_SMEM>>>();

    dim3 g3(NTOK / 128, DMODEL / 128);
    o_tc<<<g3, 256, SM_GEMM1>>>(bO, out + (size_t)BATCH * SEQ * DMODEL);
}